// round 4
// baseline (speedup 1.0000x reference)
#include <cuda_runtime.h>
#include <math.h>

#define Bsz 2
#define Tt  2048
#define Cc  2048
#define NH  8
#define HD  256
#define HH  128
#define SCALE 0.08838834764831845f   // 1/sqrt(128)

// ---------------- scratch (device globals: sanctioned, no alloc) ----------------
__device__ float g_Q [Bsz*Tt*Cc];
__device__ float g_K [Bsz*Tt*Cc];
__device__ float g_V [Bsz*Tt*Cc];
__device__ float g_q1[Bsz*NH*Tt*HH];
__device__ float g_q2[Bsz*NH*Tt*HH];
__device__ float g_k1[Bsz*NH*Tt*HH];
__device__ float g_k2[Bsz*NH*Tt*HH];
__device__ float g_vt[Bsz*NH*Tt*HD];
__device__ float g_y [Bsz*Tt*Cc];
__device__ float g_lam;

// ---------------- SGEMM: C[M,N] = alpha * A[M,K] @ B[N,K]^T (NT, row-major) ----
__global__ __launch_bounds__(256)
void sgemm_nt(const float* __restrict__ A, const float* __restrict__ B,
              float* __restrict__ C, int M, int N, int K, float alpha)
{
    __shared__ float As[16][128];
    __shared__ float Bs[16][128];
    const int tid = threadIdx.x;
    const int m0 = blockIdx.y * 128;
    const int n0 = blockIdx.x * 128;
    const int tx = tid & 15;
    const int ty = tid >> 4;
    const int lr = tid >> 2;         // 0..63
    const int lc = (tid & 3) << 2;   // 0,4,8,12
    const float* Ap = A + (size_t)(m0 + lr) * K + lc;
    const float* Bp = B + (size_t)(n0 + lr) * K + lc;

    float acc[8][8];
#pragma unroll
    for (int i = 0; i < 8; i++)
#pragma unroll
        for (int j = 0; j < 8; j++) acc[i][j] = 0.f;

    for (int k0 = 0; k0 < K; k0 += 16) {
        float4 a0 = *(const float4*)(Ap + k0);
        float4 a1 = *(const float4*)(Ap + (size_t)64 * K + k0);
        float4 b0 = *(const float4*)(Bp + k0);
        float4 b1 = *(const float4*)(Bp + (size_t)64 * K + k0);
        __syncthreads();
        As[lc+0][lr]    = a0.x; As[lc+1][lr]    = a0.y; As[lc+2][lr]    = a0.z; As[lc+3][lr]    = a0.w;
        As[lc+0][lr+64] = a1.x; As[lc+1][lr+64] = a1.y; As[lc+2][lr+64] = a1.z; As[lc+3][lr+64] = a1.w;
        Bs[lc+0][lr]    = b0.x; Bs[lc+1][lr]    = b0.y; Bs[lc+2][lr]    = b0.z; Bs[lc+3][lr]    = b0.w;
        Bs[lc+0][lr+64] = b1.x; Bs[lc+1][lr+64] = b1.y; Bs[lc+2][lr+64] = b1.z; Bs[lc+3][lr+64] = b1.w;
        __syncthreads();
#pragma unroll
        for (int kk = 0; kk < 16; kk++) {
            float a[8], b[8];
            *(float4*)(a)     = *(const float4*)&As[kk][ty*8];
            *(float4*)(a + 4) = *(const float4*)&As[kk][ty*8 + 4];
            *(float4*)(b)     = *(const float4*)&Bs[kk][tx*8];
            *(float4*)(b + 4) = *(const float4*)&Bs[kk][tx*8 + 4];
#pragma unroll
            for (int i = 0; i < 8; i++)
#pragma unroll
                for (int j = 0; j < 8; j++)
                    acc[i][j] = fmaf(a[i], b[j], acc[i][j]);
        }
    }
#pragma unroll
    for (int i = 0; i < 8; i++) {
        float* Cp = C + (size_t)(m0 + ty*8 + i) * N + n0 + tx*8;
        float4 c0 = make_float4(alpha*acc[i][0], alpha*acc[i][1], alpha*acc[i][2], alpha*acc[i][3]);
        float4 c1 = make_float4(alpha*acc[i][4], alpha*acc[i][5], alpha*acc[i][6], alpha*acc[i][7]);
        *(float4*)Cp       = c0;
        *(float4*)(Cp + 4) = c1;
    }
}

// ---------------- lambda scalar ----------------
__global__ void lam_kernel(const float* __restrict__ lq1, const float* __restrict__ lk1,
                           const float* __restrict__ lq2, const float* __restrict__ lk2)
{
    int d = threadIdx.x;             // 256 threads
    float p1 = lq1[d] * lk1[d];
    float p2 = lq2[d] * lk2[d];
#pragma unroll
    for (int o = 16; o; o >>= 1) {
        p1 += __shfl_xor_sync(0xffffffffu, p1, o);
        p2 += __shfl_xor_sync(0xffffffffu, p2, o);
    }
    __shared__ float w1[8], w2[8];
    if ((d & 31) == 0) { w1[d >> 5] = p1; w2[d >> 5] = p2; }
    __syncthreads();
    if (d == 0) {
        float s1 = 0.f, s2 = 0.f;
        for (int i = 0; i < 8; i++) { s1 += w1[i]; s2 += w2[i]; }
        g_lam = expf(s1) - expf(s2) + 0.2f;
    }
}

// ---------------- rmsnorm + (head-indexed) rotary + transpose ----------------
__device__ __forceinline__ void rot_one(const float* __restrict__ src, float* __restrict__ dst,
                                        float* sv, float* ws, float* srn, int d, float cj, float sj)
{
    float v = src[d];
    sv[d] = v;
    float sq = v * v;
#pragma unroll
    for (int o = 16; o; o >>= 1) sq += __shfl_xor_sync(0xffffffffu, sq, o);
    if ((d & 31) == 0) ws[d >> 5] = sq;
    __syncthreads();
    if (d == 0) *srn = rsqrtf((ws[0] + ws[1] + ws[2] + ws[3]) * (1.0f / 128.0f) + 1.1920929e-07f);
    __syncthreads();
    float rn = *srn;
    float vd = sv[d] * rn;
    float vp = sv[(d < 64) ? d + 64 : d - 64] * rn;
    dst[d] = (d < 64) ? (vd * cj + vp * sj) : (vd * cj - vp * sj);
    __syncthreads();
}

__global__ __launch_bounds__(128)
void prep_kernel()
{
    int idx = blockIdx.x;            // (b*T + t)*NH + h
    int h = idx & 7;
    int t = (idx >> 3) & 2047;
    int b = idx >> 14;
    int d = threadIdx.x;
    __shared__ float sv[128];
    __shared__ float ws[4];
    __shared__ float srn;

    int j = (d < 64) ? d : d - 64;
    // buggy-rotary angle: position index = head index h
    float ang = (float)h * powf(10000.0f, -(float)j * (1.0f / 64.0f));
    float cj = cosf(ang), sj = sinf(ang);

    size_t inb  = ((size_t)(b * Tt) + t) * Cc + h * HD;
    size_t outb = ((size_t)(b * NH + h) * Tt + t) * HH;

    rot_one(g_Q + inb,      g_q1 + outb, sv, ws, &srn, d, cj, sj);
    rot_one(g_Q + inb + HH, g_q2 + outb, sv, ws, &srn, d, cj, sj);
    rot_one(g_K + inb,      g_k1 + outb, sv, ws, &srn, d, cj, sj);
    rot_one(g_K + inb + HH, g_k2 + outb, sv, ws, &srn, d, cj, sj);

    const float* vsrc = g_V + inb;
    float* vdst = g_vt + ((size_t)(b * NH + h) * Tt + t) * HD;
    vdst[d]       = vsrc[d];
    vdst[d + 128] = vsrc[d + 128];
}

// ---------------- dual causal flash attention (fp32) ----------------
// grid: (T/16, B*NH), block 512 = 16 warps, 1 query per warp, 32-key tiles.
__global__ __launch_bounds__(512)
void attn_kernel()
{
    extern __shared__ float sm[];
    float (*k1s)[129] = (float(*)[129])(sm);
    float (*k2s)[129] = (float(*)[129])(sm + 32 * 129);
    float (*vsm)[256] = (float(*)[256])(sm + 2 * 32 * 129);
    float (*q1s)[128] = (float(*)[128])(sm + 2 * 32 * 129 + 32 * 256);
    float (*q2s)[128] = (float(*)[128])(sm + 2 * 32 * 129 + 32 * 256 + 16 * 128);

    const int tid  = threadIdx.x;
    const int lane = tid & 31;
    const int w    = tid >> 5;
    const int bh   = blockIdx.y;
    const int t    = blockIdx.x * 16 + w;

    const float* q1p = g_q1 + ((size_t)bh * Tt + t) * HH;
    const float* q2p = g_q2 + ((size_t)bh * Tt + t) * HH;
    ((float4*)q1s[w])[lane] = ((const float4*)q1p)[lane];
    ((float4*)q2s[w])[lane] = ((const float4*)q2p)[lane];
    __syncwarp();

    float m1 = -1e30f, m2 = -1e30f, l1 = 0.f, l2 = 0.f;
    float acc1[8], acc2[8];
#pragma unroll
    for (int i = 0; i < 8; i++) { acc1[i] = 0.f; acc2[i] = 0.f; }

    const int ntiles = (blockIdx.x * 16 + 15) / 32 + 1;
    const float* k1b = g_k1 + (size_t)bh * Tt * HH;
    const float* k2b = g_k2 + (size_t)bh * Tt * HH;
    const float* vb  = g_vt + (size_t)bh * Tt * HD;

    const int row = tid >> 4;        // 0..31
    const int cg  = tid & 15;

    for (int kb = 0; kb < ntiles; kb++) {
        __syncthreads();
        {
            const float* s1 = k1b + (size_t)(kb * 32 + row) * HH + cg * 8;
            float4 x0 = ((const float4*)s1)[0];
            float4 x1 = ((const float4*)s1)[1];
            float* dp = &k1s[row][cg * 8];
            dp[0]=x0.x; dp[1]=x0.y; dp[2]=x0.z; dp[3]=x0.w;
            dp[4]=x1.x; dp[5]=x1.y; dp[6]=x1.z; dp[7]=x1.w;

            const float* s2 = k2b + (size_t)(kb * 32 + row) * HH + cg * 8;
            float4 y0 = ((const float4*)s2)[0];
            float4 y1 = ((const float4*)s2)[1];
            float* dq = &k2s[row][cg * 8];
            dq[0]=y0.x; dq[1]=y0.y; dq[2]=y0.z; dq[3]=y0.w;
            dq[4]=y1.x; dq[5]=y1.y; dq[6]=y1.z; dq[7]=y1.w;

            const float* sv = vb + (size_t)(kb * 32 + row) * HD + cg * 16;
            float4* dv = (float4*)&vsm[row][cg * 16];
            dv[0] = ((const float4*)sv)[0];
            dv[1] = ((const float4*)sv)[1];
            dv[2] = ((const float4*)sv)[2];
            dv[3] = ((const float4*)sv)[3];
        }
        __syncthreads();

        int krem = t - kb * 32 + 1;
        if (krem > 0) {
            int nk = krem < 32 ? krem : 32;
            float s1 = 0.f, s2 = 0.f;
            const float* kr1 = k1s[lane];
            const float* kr2 = k2s[lane];
            const float* qa  = q1s[w];
            const float* qb  = q2s[w];
#pragma unroll 16
            for (int d = 0; d < HH; d++) {
                s1 = fmaf(qa[d], kr1[d], s1);
                s2 = fmaf(qb[d], kr2[d], s2);
            }
            s1 *= SCALE; s2 *= SCALE;
            if (lane >= nk) { s1 = -1e30f; s2 = -1e30f; }

            float mx1 = s1, mx2 = s2;
#pragma unroll
            for (int o = 16; o; o >>= 1) {
                mx1 = fmaxf(mx1, __shfl_xor_sync(0xffffffffu, mx1, o));
                mx2 = fmaxf(mx2, __shfl_xor_sync(0xffffffffu, mx2, o));
            }
            float nm1 = fmaxf(m1, mx1), nm2 = fmaxf(m2, mx2);
            float p1 = __expf(s1 - nm1), p2 = __expf(s2 - nm2);
            float c1 = __expf(m1 - nm1), c2 = __expf(m2 - nm2);
            float sp1 = p1, sp2 = p2;
#pragma unroll
            for (int o = 16; o; o >>= 1) {
                sp1 += __shfl_xor_sync(0xffffffffu, sp1, o);
                sp2 += __shfl_xor_sync(0xffffffffu, sp2, o);
            }
            l1 = l1 * c1 + sp1; l2 = l2 * c2 + sp2;
            m1 = nm1; m2 = nm2;
#pragma unroll
            for (int i = 0; i < 8; i++) { acc1[i] *= c1; acc2[i] *= c2; }

#pragma unroll 4
            for (int jj = 0; jj < 32; jj++) {
                float pj1 = __shfl_sync(0xffffffffu, p1, jj);
                float pj2 = __shfl_sync(0xffffffffu, p2, jj);
                const float* vr = vsm[jj];
#pragma unroll
                for (int i = 0; i < 8; i++) {
                    float vv = vr[lane + 32 * i];
                    acc1[i] = fmaf(pj1, vv, acc1[i]);
                    acc2[i] = fmaf(pj2, vv, acc2[i]);
                }
            }
        }
    }

    float lam = g_lam;
    float r1 = 1.f / l1, r2 = lam / l2;
    int b = bh >> 3, h = bh & 7;
    float* yp = g_y + ((size_t)(b * Tt) + t) * Cc + h * HD;
#pragma unroll
    for (int i = 0; i < 8; i++)
        yp[lane + 32 * i] = acc1[i] * r1 - acc2[i] * r2;
}

// ---------------- launcher ----------------
extern "C" void kernel_launch(void* const* d_in, const int* in_sizes, int n_in,
                              void* d_out, int out_size)
{
    const float* x   = (const float*)d_in[0];
    const float* wq  = (const float*)d_in[1];
    const float* wk  = (const float*)d_in[2];
    const float* wv  = (const float*)d_in[3];
    const float* wo  = (const float*)d_in[4];
    const float* lq1 = (const float*)d_in[5];
    const float* lk1 = (const float*)d_in[6];
    const float* lq2 = (const float*)d_in[7];
    const float* lk2 = (const float*)d_in[8];
    float* out = (float*)d_out;

    void *pQ, *pK, *pV, *pY;
    cudaGetSymbolAddress(&pQ, g_Q);
    cudaGetSymbolAddress(&pK, g_K);
    cudaGetSymbolAddress(&pV, g_V);
    cudaGetSymbolAddress(&pY, g_y);

    dim3 gg(Cc / 128, (Bsz * Tt) / 128);
    sgemm_nt<<<gg, 256>>>(x, wq, (float*)pQ, Bsz * Tt, Cc, Cc, 1.0f);
    sgemm_nt<<<gg, 256>>>(x, wk, (float*)pK, Bsz * Tt, Cc, Cc, 1.0f);
    sgemm_nt<<<gg, 256>>>(x, wv, (float*)pV, Bsz * Tt, Cc, Cc, 1.0f);
    lam_kernel<<<1, 256>>>(lq1, lk1, lq2, lk2);
    prep_kernel<<<Bsz * Tt * NH, 128>>>();

    int smem = (2 * 32 * 129 + 32 * 256 + 2 * 16 * 128) * 4;  // 82176 B
    cudaFuncSetAttribute(attn_kernel, cudaFuncAttributeMaxDynamicSharedMemorySize, smem);
    attn_kernel<<<dim3(Tt / 16, Bsz * NH), 512, smem>>>();

    sgemm_nt<<<gg, 256>>>((const float*)pY, wo, out, Bsz * Tt, Cc, Cc, 0.8f);
}

// round 5
// speedup vs baseline: 1.3939x; 1.3939x over previous
#include <cuda_runtime.h>
#include <math.h>

#define Bsz 2
#define Tt  2048
#define Cc  2048
#define NH  8
#define HD  256
#define HH  128
#define SCALE 0.08838834764831845f   // 1/sqrt(128)

// ---------------- scratch (device globals: sanctioned, no alloc) ----------------
__device__ float g_Q [Bsz*Tt*Cc];
__device__ float g_K [Bsz*Tt*Cc];
__device__ float g_V [Bsz*Tt*Cc];
__device__ float g_q1[Bsz*NH*Tt*HH];
__device__ float g_q2[Bsz*NH*Tt*HH];
__device__ float g_k1[Bsz*NH*Tt*HH];
__device__ float g_k2[Bsz*NH*Tt*HH];
__device__ float g_vt[Bsz*NH*Tt*HD];
__device__ float g_y [Bsz*Tt*Cc];
__device__ float g_lam;

// ---------------- helpers ----------------
__device__ __forceinline__ unsigned f2tf32(float x) {
    unsigned r;
    asm("cvt.rna.tf32.f32 %0, %1;" : "=r"(r) : "f"(x));
    return r;
}

__device__ __forceinline__ void mma_tf32(float* d, const unsigned* a, const unsigned* b) {
    asm volatile(
        "mma.sync.aligned.m16n8k8.row.col.f32.tf32.tf32.f32 "
        "{%0,%1,%2,%3}, {%4,%5,%6,%7}, {%8,%9}, {%0,%1,%2,%3};"
        : "+f"(d[0]), "+f"(d[1]), "+f"(d[2]), "+f"(d[3])
        : "r"(a[0]), "r"(a[1]), "r"(a[2]), "r"(a[3]), "r"(b[0]), "r"(b[1]));
}

// ---------------- TF32 GEMM: C[M,N] = alpha * A[M,K] @ B[N,K]^T ----------------
// block tile 128x128x32, 8 warps (2x4), warp tile 64x32, mma m16n8k8 tf32.
#define PAD 133
__global__ __launch_bounds__(256, 2)
void tgemm_nt(const float* __restrict__ A, const float* __restrict__ B,
              float* __restrict__ C, int M, int N, int K, float alpha)
{
    __shared__ unsigned As[32 * PAD];
    __shared__ unsigned Bs[32 * PAD];

    const int tid  = threadIdx.x;
    const int wid  = tid >> 5;
    const int lane = tid & 31;
    const int wm   = (wid & 1) * 64;     // warp row offset within block tile
    const int wn   = (wid >> 1) * 32;    // warp col offset
    const int r    = lane >> 2;          // 0..7
    const int c    = lane & 3;           // 0..3

    const int m0 = blockIdx.y * 128;
    const int n0 = blockIdx.x * 128;

    const int ar = tid >> 3;             // 0..31
    const int ac = (tid & 7) * 4;        // 0,4,...,28

    const float* Ap = A + (size_t)(m0 + ar) * K + ac;
    const float* Bp = B + (size_t)(n0 + ar) * K + ac;

    float acc[4][4][4];
#pragma unroll
    for (int i = 0; i < 4; i++)
#pragma unroll
        for (int j = 0; j < 4; j++)
#pragma unroll
            for (int e = 0; e < 4; e++) acc[i][j][e] = 0.f;

    for (int k0 = 0; k0 < K; k0 += 32) {
        float4 av[4], bv[4];
#pragma unroll
        for (int i = 0; i < 4; i++) {
            av[i] = *(const float4*)(Ap + (size_t)(32 * i) * K + k0);
            bv[i] = *(const float4*)(Bp + (size_t)(32 * i) * K + k0);
        }
        __syncthreads();
#pragma unroll
        for (int i = 0; i < 4; i++) {
            int m = ar + 32 * i;
            As[(ac + 0) * PAD + m] = f2tf32(av[i].x);
            As[(ac + 1) * PAD + m] = f2tf32(av[i].y);
            As[(ac + 2) * PAD + m] = f2tf32(av[i].z);
            As[(ac + 3) * PAD + m] = f2tf32(av[i].w);
            Bs[(ac + 0) * PAD + m] = f2tf32(bv[i].x);
            Bs[(ac + 1) * PAD + m] = f2tf32(bv[i].y);
            Bs[(ac + 2) * PAD + m] = f2tf32(bv[i].z);
            Bs[(ac + 3) * PAD + m] = f2tf32(bv[i].w);
        }
        __syncthreads();

#pragma unroll
        for (int ks = 0; ks < 4; ks++) {
            const unsigned* Ab = As + (ks * 8 + c) * PAD;
            const unsigned* Bb = Bs + (ks * 8 + c) * PAD;
            unsigned af[4][4], bf[4][2];
#pragma unroll
            for (int mi = 0; mi < 4; mi++) {
                af[mi][0] = Ab[wm + 16 * mi + r];
                af[mi][1] = Ab[wm + 16 * mi + r + 8];
                af[mi][2] = Ab[4 * PAD + wm + 16 * mi + r];
                af[mi][3] = Ab[4 * PAD + wm + 16 * mi + r + 8];
            }
#pragma unroll
            for (int nj = 0; nj < 4; nj++) {
                bf[nj][0] = Bb[wn + 8 * nj + r];
                bf[nj][1] = Bb[4 * PAD + wn + 8 * nj + r];
            }
#pragma unroll
            for (int mi = 0; mi < 4; mi++)
#pragma unroll
                for (int nj = 0; nj < 4; nj++)
                    mma_tf32(acc[mi][nj], af[mi], bf[nj]);
        }
    }

#pragma unroll
    for (int mi = 0; mi < 4; mi++) {
#pragma unroll
        for (int nj = 0; nj < 4; nj++) {
            int row = m0 + wm + 16 * mi + r;
            int col = n0 + wn + 8 * nj + 2 * c;
            *(float2*)(C + (size_t)row * N + col) =
                make_float2(alpha * acc[mi][nj][0], alpha * acc[mi][nj][1]);
            *(float2*)(C + (size_t)(row + 8) * N + col) =
                make_float2(alpha * acc[mi][nj][2], alpha * acc[mi][nj][3]);
        }
    }
}

// ---------------- lambda scalar ----------------
__global__ void lam_kernel(const float* __restrict__ lq1, const float* __restrict__ lk1,
                           const float* __restrict__ lq2, const float* __restrict__ lk2)
{
    int d = threadIdx.x;             // 256 threads
    float p1 = lq1[d] * lk1[d];
    float p2 = lq2[d] * lk2[d];
#pragma unroll
    for (int o = 16; o; o >>= 1) {
        p1 += __shfl_xor_sync(0xffffffffu, p1, o);
        p2 += __shfl_xor_sync(0xffffffffu, p2, o);
    }
    __shared__ float w1[8], w2[8];
    if ((d & 31) == 0) { w1[d >> 5] = p1; w2[d >> 5] = p2; }
    __syncthreads();
    if (d == 0) {
        float s1 = 0.f, s2 = 0.f;
        for (int i = 0; i < 8; i++) { s1 += w1[i]; s2 += w2[i]; }
        g_lam = expf(s1) - expf(s2) + 0.2f;
    }
}

// ---------------- rmsnorm + (head-indexed) rotary + transpose, warp-level ----
// block 128 = 4 warps: warp 0->q1, 1->q2, 2->k1, 3->k2. One (b,t,h) per block.
__global__ __launch_bounds__(128)
void prep_kernel()
{
    int idx = blockIdx.x;            // (b*T + t)*NH + h
    int h = idx & 7;
    int t = (idx >> 3) & 2047;
    int b = idx >> 14;
    int tid  = threadIdx.x;
    int w    = tid >> 5;
    int lane = tid & 31;

    size_t inb  = ((size_t)(b * Tt) + t) * Cc + h * HD;
    size_t outb = ((size_t)(b * NH + h) * Tt + t) * HH;

    const float* src;
    float* dst;
    if      (w == 0) { src = g_Q + inb;      dst = g_q1 + outb; }
    else if (w == 1) { src = g_Q + inb + HH; dst = g_q2 + outb; }
    else if (w == 2) { src = g_K + inb;      dst = g_k1 + outb; }
    else             { src = g_K + inb + HH; dst = g_k2 + outb; }

    float4 v = ((const float4*)src)[lane];
    float sq = v.x*v.x + v.y*v.y + v.z*v.z + v.w*v.w;
#pragma unroll
    for (int o = 16; o; o >>= 1) sq += __shfl_xor_sync(0xffffffffu, sq, o);
    float rn = rsqrtf(sq * (1.0f / 128.0f) + 1.1920929e-07f);

    // partner half (d <-> d+64) lives in lane ^ 16
    float4 p;
    p.x = __shfl_xor_sync(0xffffffffu, v.x, 16);
    p.y = __shfl_xor_sync(0xffffffffu, v.y, 16);
    p.z = __shfl_xor_sync(0xffffffffu, v.z, 16);
    p.w = __shfl_xor_sync(0xffffffffu, v.w, 16);

    bool first = lane < 16;
    int j0 = first ? 4 * lane : 4 * (lane - 16);
    float vv[4] = {v.x, v.y, v.z, v.w};
    float pp[4] = {p.x, p.y, p.z, p.w};
    float out[4];
#pragma unroll
    for (int i = 0; i < 4; i++) {
        // buggy-rotary angle: position index = head index h
        float ang = (float)h * exp2f(-(float)(j0 + i) * (13.287712379549449f / 64.0f));
        float cj = cosf(ang), sj = sinf(ang);
        float vd = vv[i] * rn, vp = pp[i] * rn;
        out[i] = first ? (vd * cj + vp * sj) : (vd * cj - vp * sj);
    }
    ((float4*)dst)[lane] = make_float4(out[0], out[1], out[2], out[3]);

    // V copy: threads 0..63 move 256 floats
    if (tid < 64) {
        const float* vsrc = g_V + inb;
        float* vdst = g_vt + ((size_t)(b * NH + h) * Tt + t) * HD;
        ((float4*)vdst)[tid] = ((const float4*)vsrc)[tid];
    }
}

// ---------------- dual causal flash attention (fp32) ----------------
// grid: (T/16, B*NH), block 512 = 16 warps, 1 query per warp, 32-key tiles.
__global__ __launch_bounds__(512)
void attn_kernel()
{
    extern __shared__ float sm[];
    float (*k1s)[129] = (float(*)[129])(sm);
    float (*k2s)[129] = (float(*)[129])(sm + 32 * 129);
    float (*vsm)[256] = (float(*)[256])(sm + 2 * 32 * 129);
    float (*q1s)[128] = (float(*)[128])(sm + 2 * 32 * 129 + 32 * 256);
    float (*q2s)[128] = (float(*)[128])(sm + 2 * 32 * 129 + 32 * 256 + 16 * 128);

    const int tid  = threadIdx.x;
    const int lane = tid & 31;
    const int w    = tid >> 5;
    const int bh   = blockIdx.y;
    const int t    = blockIdx.x * 16 + w;

    const float* q1p = g_q1 + ((size_t)bh * Tt + t) * HH;
    const float* q2p = g_q2 + ((size_t)bh * Tt + t) * HH;
    ((float4*)q1s[w])[lane] = ((const float4*)q1p)[lane];
    ((float4*)q2s[w])[lane] = ((const float4*)q2p)[lane];
    __syncwarp();

    float m1 = -1e30f, m2 = -1e30f, l1 = 0.f, l2 = 0.f;
    float acc1[8], acc2[8];
#pragma unroll
    for (int i = 0; i < 8; i++) { acc1[i] = 0.f; acc2[i] = 0.f; }

    const int ntiles = (blockIdx.x * 16 + 15) / 32 + 1;
    const float* k1b = g_k1 + (size_t)bh * Tt * HH;
    const float* k2b = g_k2 + (size_t)bh * Tt * HH;
    const float* vb  = g_vt + (size_t)bh * Tt * HD;

    const int row = tid >> 4;        // 0..31
    const int cg  = tid & 15;

    for (int kb = 0; kb < ntiles; kb++) {
        __syncthreads();
        {
            const float* s1 = k1b + (size_t)(kb * 32 + row) * HH + cg * 8;
            float4 x0 = ((const float4*)s1)[0];
            float4 x1 = ((const float4*)s1)[1];
            float* dp = &k1s[row][cg * 8];
            dp[0]=x0.x; dp[1]=x0.y; dp[2]=x0.z; dp[3]=x0.w;
            dp[4]=x1.x; dp[5]=x1.y; dp[6]=x1.z; dp[7]=x1.w;

            const float* s2 = k2b + (size_t)(kb * 32 + row) * HH + cg * 8;
            float4 y0 = ((const float4*)s2)[0];
            float4 y1 = ((const float4*)s2)[1];
            float* dq = &k2s[row][cg * 8];
            dq[0]=y0.x; dq[1]=y0.y; dq[2]=y0.z; dq[3]=y0.w;
            dq[4]=y1.x; dq[5]=y1.y; dq[6]=y1.z; dq[7]=y1.w;

            const float* sv = vb + (size_t)(kb * 32 + row) * HD + cg * 16;
            float4* dv = (float4*)&vsm[row][cg * 16];
            dv[0] = ((const float4*)sv)[0];
            dv[1] = ((const float4*)sv)[1];
            dv[2] = ((const float4*)sv)[2];
            dv[3] = ((const float4*)sv)[3];
        }
        __syncthreads();

        int krem = t - kb * 32 + 1;
        if (krem > 0) {
            int nk = krem < 32 ? krem : 32;
            float s1 = 0.f, s2 = 0.f;
            const float* kr1 = k1s[lane];
            const float* kr2 = k2s[lane];
            const float* qa  = q1s[w];
            const float* qb  = q2s[w];
#pragma unroll 16
            for (int d = 0; d < HH; d++) {
                s1 = fmaf(qa[d], kr1[d], s1);
                s2 = fmaf(qb[d], kr2[d], s2);
            }
            s1 *= SCALE; s2 *= SCALE;
            if (lane >= nk) { s1 = -1e30f; s2 = -1e30f; }

            float mx1 = s1, mx2 = s2;
#pragma unroll
            for (int o = 16; o; o >>= 1) {
                mx1 = fmaxf(mx1, __shfl_xor_sync(0xffffffffu, mx1, o));
                mx2 = fmaxf(mx2, __shfl_xor_sync(0xffffffffu, mx2, o));
            }
            float nm1 = fmaxf(m1, mx1), nm2 = fmaxf(m2, mx2);
            float p1 = __expf(s1 - nm1), p2 = __expf(s2 - nm2);
            float c1 = __expf(m1 - nm1), c2 = __expf(m2 - nm2);
            float sp1 = p1, sp2 = p2;
#pragma unroll
            for (int o = 16; o; o >>= 1) {
                sp1 += __shfl_xor_sync(0xffffffffu, sp1, o);
                sp2 += __shfl_xor_sync(0xffffffffu, sp2, o);
            }
            l1 = l1 * c1 + sp1; l2 = l2 * c2 + sp2;
            m1 = nm1; m2 = nm2;
#pragma unroll
            for (int i = 0; i < 8; i++) { acc1[i] *= c1; acc2[i] *= c2; }

#pragma unroll 4
            for (int jj = 0; jj < 32; jj++) {
                float pj1 = __shfl_sync(0xffffffffu, p1, jj);
                float pj2 = __shfl_sync(0xffffffffu, p2, jj);
                const float* vr = vsm[jj];
#pragma unroll
                for (int i = 0; i < 8; i++) {
                    float vv = vr[lane + 32 * i];
                    acc1[i] = fmaf(pj1, vv, acc1[i]);
                    acc2[i] = fmaf(pj2, vv, acc2[i]);
                }
            }
        }
    }

    float lam = g_lam;
    float r1 = 1.f / l1, r2 = lam / l2;
    int b = bh >> 3, h = bh & 7;
    float* yp = g_y + ((size_t)(b * Tt) + t) * Cc + h * HD;
#pragma unroll
    for (int i = 0; i < 8; i++)
        yp[lane + 32 * i] = acc1[i] * r1 - acc2[i] * r2;
}

// ---------------- launcher ----------------
extern "C" void kernel_launch(void* const* d_in, const int* in_sizes, int n_in,
                              void* d_out, int out_size)
{
    const float* x   = (const float*)d_in[0];
    const float* wq  = (const float*)d_in[1];
    const float* wk  = (const float*)d_in[2];
    const float* wv  = (const float*)d_in[3];
    const float* wo  = (const float*)d_in[4];
    const float* lq1 = (const float*)d_in[5];
    const float* lk1 = (const float*)d_in[6];
    const float* lq2 = (const float*)d_in[7];
    const float* lk2 = (const float*)d_in[8];
    float* out = (float*)d_out;

    void *pQ, *pK, *pV, *pY;
    cudaGetSymbolAddress(&pQ, g_Q);
    cudaGetSymbolAddress(&pK, g_K);
    cudaGetSymbolAddress(&pV, g_V);
    cudaGetSymbolAddress(&pY, g_y);

    dim3 gg(Cc / 128, (Bsz * Tt) / 128);
    tgemm_nt<<<gg, 256>>>(x, wq, (float*)pQ, Bsz * Tt, Cc, Cc, 1.0f);
    tgemm_nt<<<gg, 256>>>(x, wk, (float*)pK, Bsz * Tt, Cc, Cc, 1.0f);
    tgemm_nt<<<gg, 256>>>(x, wv, (float*)pV, Bsz * Tt, Cc, Cc, 1.0f);
    lam_kernel<<<1, 256>>>(lq1, lk1, lq2, lk2);
    prep_kernel<<<Bsz * Tt * NH, 128>>>();

    int smem = (2 * 32 * 129 + 32 * 256 + 2 * 16 * 128) * 4;  // 82176 B
    cudaFuncSetAttribute(attn_kernel, cudaFuncAttributeMaxDynamicSharedMemorySize, smem);
    attn_kernel<<<dim3(Tt / 16, Bsz * NH), 512, smem>>>();

    tgemm_nt<<<gg, 256>>>((const float*)pY, wo, out, Bsz * Tt, Cc, Cc, 0.8f);
}

// round 6
// speedup vs baseline: 4.0757x; 2.9239x over previous
#include <cuda_runtime.h>
#include <math.h>

#define Bsz 2
#define Tt  2048
#define Cc  2048
#define NH  8
#define HD  256
#define HH  128
#define SCALE 0.08838834764831845f   // 1/sqrt(128)

// ---------------- scratch (device globals: sanctioned, no alloc) ----------------
__device__ float g_Q [Bsz*Tt*Cc];
__device__ float g_K [Bsz*Tt*Cc];
__device__ float g_V [Bsz*Tt*Cc];
__device__ float g_q1[Bsz*NH*Tt*HH];
__device__ float g_q2[Bsz*NH*Tt*HH];
__device__ float g_k1[Bsz*NH*Tt*HH];
__device__ float g_k2[Bsz*NH*Tt*HH];
__device__ float g_y [Bsz*Tt*Cc];
__device__ float g_lam;

// ---------------- helpers ----------------
__device__ __forceinline__ unsigned f2tf32(float x) {
    unsigned r;
    asm("cvt.rna.tf32.f32 %0, %1;" : "=r"(r) : "f"(x));
    return r;
}

__device__ __forceinline__ void mma_tf32(float* d, const unsigned* a, const unsigned* b) {
    asm volatile(
        "mma.sync.aligned.m16n8k8.row.col.f32.tf32.tf32.f32 "
        "{%0,%1,%2,%3}, {%4,%5,%6,%7}, {%8,%9}, {%0,%1,%2,%3};"
        : "+f"(d[0]), "+f"(d[1]), "+f"(d[2]), "+f"(d[3])
        : "r"(a[0]), "r"(a[1]), "r"(a[2]), "r"(a[3]), "r"(b[0]), "r"(b[1]));
}

// ---------------- TF32 GEMM body: C = alpha * A[M,K] @ B[N,K]^T ----------------
#define PAD 133
__device__ __forceinline__
void tgemm_body(const float* __restrict__ A, const float* __restrict__ B,
                float* __restrict__ C, int N, int K, float alpha,
                unsigned* As, unsigned* Bs)
{
    const int tid  = threadIdx.x;
    const int wid  = tid >> 5;
    const int lane = tid & 31;
    const int wm   = (wid & 1) * 64;
    const int wn   = (wid >> 1) * 32;
    const int r    = lane >> 2;
    const int c    = lane & 3;

    const int m0 = blockIdx.y * 128;
    const int n0 = blockIdx.x * 128;

    const int ar = tid >> 3;
    const int ac = (tid & 7) * 4;

    const float* Ap = A + (size_t)(m0 + ar) * K + ac;
    const float* Bp = B + (size_t)(n0 + ar) * K + ac;

    float acc[4][4][4];
#pragma unroll
    for (int i = 0; i < 4; i++)
#pragma unroll
        for (int j = 0; j < 4; j++)
#pragma unroll
            for (int e = 0; e < 4; e++) acc[i][j][e] = 0.f;

    for (int k0 = 0; k0 < K; k0 += 32) {
        float4 av[4], bv[4];
#pragma unroll
        for (int i = 0; i < 4; i++) {
            av[i] = *(const float4*)(Ap + (size_t)(32 * i) * K + k0);
            bv[i] = *(const float4*)(Bp + (size_t)(32 * i) * K + k0);
        }
        __syncthreads();
#pragma unroll
        for (int i = 0; i < 4; i++) {
            int m = ar + 32 * i;
            As[(ac + 0) * PAD + m] = f2tf32(av[i].x);
            As[(ac + 1) * PAD + m] = f2tf32(av[i].y);
            As[(ac + 2) * PAD + m] = f2tf32(av[i].z);
            As[(ac + 3) * PAD + m] = f2tf32(av[i].w);
            Bs[(ac + 0) * PAD + m] = f2tf32(bv[i].x);
            Bs[(ac + 1) * PAD + m] = f2tf32(bv[i].y);
            Bs[(ac + 2) * PAD + m] = f2tf32(bv[i].z);
            Bs[(ac + 3) * PAD + m] = f2tf32(bv[i].w);
        }
        __syncthreads();

#pragma unroll
        for (int ks = 0; ks < 4; ks++) {
            const unsigned* Ab = As + (ks * 8 + c) * PAD;
            const unsigned* Bb = Bs + (ks * 8 + c) * PAD;
            unsigned af[4][4], bf[4][2];
#pragma unroll
            for (int mi = 0; mi < 4; mi++) {
                af[mi][0] = Ab[wm + 16 * mi + r];
                af[mi][1] = Ab[wm + 16 * mi + r + 8];
                af[mi][2] = Ab[4 * PAD + wm + 16 * mi + r];
                af[mi][3] = Ab[4 * PAD + wm + 16 * mi + r + 8];
            }
#pragma unroll
            for (int nj = 0; nj < 4; nj++) {
                bf[nj][0] = Bb[wn + 8 * nj + r];
                bf[nj][1] = Bb[4 * PAD + wn + 8 * nj + r];
            }
#pragma unroll
            for (int mi = 0; mi < 4; mi++)
#pragma unroll
                for (int nj = 0; nj < 4; nj++)
                    mma_tf32(acc[mi][nj], af[mi], bf[nj]);
        }
    }

#pragma unroll
    for (int mi = 0; mi < 4; mi++) {
#pragma unroll
        for (int nj = 0; nj < 4; nj++) {
            int row = m0 + wm + 16 * mi + r;
            int col = n0 + wn + 8 * nj + 2 * c;
            *(float2*)(C + (size_t)row * N + col) =
                make_float2(alpha * acc[mi][nj][0], alpha * acc[mi][nj][1]);
            *(float2*)(C + (size_t)(row + 8) * N + col) =
                make_float2(alpha * acc[mi][nj][2], alpha * acc[mi][nj][3]);
        }
    }
}

__global__ __launch_bounds__(256, 2)
void tgemm_nt(const float* __restrict__ A, const float* __restrict__ B,
              float* __restrict__ C, int N, int K, float alpha)
{
    __shared__ unsigned As[32 * PAD];
    __shared__ unsigned Bs[32 * PAD];
    tgemm_body(A, B, C, N, K, alpha, As, Bs);
}

// fused Q/K/V projection: blockIdx.z selects weight + destination
__global__ __launch_bounds__(256, 2)
void tgemm_qkv(const float* __restrict__ A, const float* __restrict__ Wq,
               const float* __restrict__ Wk, const float* __restrict__ Wv)
{
    __shared__ unsigned As[32 * PAD];
    __shared__ unsigned Bs[32 * PAD];
    const float* B = (blockIdx.z == 0) ? Wq : (blockIdx.z == 1) ? Wk : Wv;
    float* C = (blockIdx.z == 0) ? g_Q : (blockIdx.z == 1) ? g_K : g_V;
    tgemm_body(A, B, C, Cc, Cc, 1.0f, As, Bs);
}

// ---------------- lambda scalar ----------------
__global__ void lam_kernel(const float* __restrict__ lq1, const float* __restrict__ lk1,
                           const float* __restrict__ lq2, const float* __restrict__ lk2)
{
    int d = threadIdx.x;             // 256 threads
    float p1 = lq1[d] * lk1[d];
    float p2 = lq2[d] * lk2[d];
#pragma unroll
    for (int o = 16; o; o >>= 1) {
        p1 += __shfl_xor_sync(0xffffffffu, p1, o);
        p2 += __shfl_xor_sync(0xffffffffu, p2, o);
    }
    __shared__ float w1[8], w2[8];
    if ((d & 31) == 0) { w1[d >> 5] = p1; w2[d >> 5] = p2; }
    __syncthreads();
    if (d == 0) {
        float s1 = 0.f, s2 = 0.f;
        for (int i = 0; i < 8; i++) { s1 += w1[i]; s2 += w2[i]; }
        g_lam = expf(s1) - expf(s2) + 0.2f;
    }
}

// ---------------- rmsnorm + (head-indexed) rotary + transpose, warp-level ----
__global__ __launch_bounds__(128)
void prep_kernel()
{
    int idx = blockIdx.x;            // (b*T + t)*NH + h
    int h = idx & 7;
    int t = (idx >> 3) & 2047;
    int b = idx >> 14;
    int tid  = threadIdx.x;
    int w    = tid >> 5;
    int lane = tid & 31;

    size_t inb  = ((size_t)(b * Tt) + t) * Cc + h * HD;
    size_t outb = ((size_t)(b * NH + h) * Tt + t) * HH;

    const float* src;
    float* dst;
    if      (w == 0) { src = g_Q + inb;      dst = g_q1 + outb; }
    else if (w == 1) { src = g_Q + inb + HH; dst = g_q2 + outb; }
    else if (w == 2) { src = g_K + inb;      dst = g_k1 + outb; }
    else             { src = g_K + inb + HH; dst = g_k2 + outb; }

    float4 v = ((const float4*)src)[lane];
    float sq = v.x*v.x + v.y*v.y + v.z*v.z + v.w*v.w;
#pragma unroll
    for (int o = 16; o; o >>= 1) sq += __shfl_xor_sync(0xffffffffu, sq, o);
    float rn = rsqrtf(sq * (1.0f / 128.0f) + 1.1920929e-07f);

    float4 p;
    p.x = __shfl_xor_sync(0xffffffffu, v.x, 16);
    p.y = __shfl_xor_sync(0xffffffffu, v.y, 16);
    p.z = __shfl_xor_sync(0xffffffffu, v.z, 16);
    p.w = __shfl_xor_sync(0xffffffffu, v.w, 16);

    bool first = lane < 16;
    int j0 = first ? 4 * lane : 4 * (lane - 16);
    float vv[4] = {v.x, v.y, v.z, v.w};
    float pp[4] = {p.x, p.y, p.z, p.w};
    float out[4];
#pragma unroll
    for (int i = 0; i < 4; i++) {
        // buggy-rotary angle: position index = head index h
        float ang = (float)h * exp2f(-(float)(j0 + i) * (13.287712379549449f / 64.0f));
        float cj = cosf(ang), sj = sinf(ang);
        float vd = vv[i] * rn, vp = pp[i] * rn;
        out[i] = first ? (vd * cj + vp * sj) : (vd * cj - vp * sj);
    }
    ((float4*)dst)[lane] = make_float4(out[0], out[1], out[2], out[3]);
}

// ---------------- tensor-core dual causal flash attention ----------------
// grid (16 bh, 32 qtiles reversed), 256 thr = 8 warps = 4 M-strips x 2 branches.
// Each warp owns 16 q-rows of one branch: S(16x64) mma, warp-local softmax,
// P->A-frag via shfl, PV(16x256) mma. Branches combined via smem exchange.
__global__ __launch_bounds__(256, 1)
void attn_tc()
{
    extern __shared__ float smf[];
    unsigned* q_s = (unsigned*)smf;        // [2][64][132]
    unsigned* k_s = q_s + 16896;           // [2][64][132]
    unsigned* v_s = k_s + 16896;           // [64][264]

    const int tid   = threadIdx.x;
    const int lane  = tid & 31;
    const int w     = tid >> 5;
    const int g     = lane >> 2;
    const int t     = lane & 3;
    const int br    = w & 1;
    const int strip = w >> 1;
    const int mrow  = strip * 16;
    const int bh    = blockIdx.x;
    const int qt    = (int)gridDim.y - 1 - (int)blockIdx.y;  // big tiles first
    const int q0    = qt * 64;

    const float QSC = SCALE * 1.4426950408889634f;   // fold scale + log2(e)

    // load Q tile (both branches), scaled, tf32
    for (int i = tid; i < 4096; i += 256) {
        int bq = i >> 11;
        int r  = (i >> 5) & 63;
        int c4 = (i & 31) << 2;
        const float* src = (bq ? g_q2 : g_q1) + ((size_t)bh * Tt + q0 + r) * HH + c4;
        float4 v = *(const float4*)src;
        uint4 u;
        u.x = f2tf32(v.x * QSC); u.y = f2tf32(v.y * QSC);
        u.z = f2tf32(v.z * QSC); u.w = f2tf32(v.w * QSC);
        *(uint4*)&q_s[bq * 8448 + r * 132 + c4] = u;
    }

    float oa[32][4];
#pragma unroll
    for (int i = 0; i < 32; i++) { oa[i][0]=0.f; oa[i][1]=0.f; oa[i][2]=0.f; oa[i][3]=0.f; }
    float m0 = -1e30f, m1 = -1e30f, l0 = 0.f, l1 = 0.f;

    const int b_ = bh >> 3, h_ = bh & 7;
    const float* vsrc = g_V + (size_t)(b_ * Tt) * Cc + h_ * HD;

    for (int kb = 0; kb <= qt; kb++) {
        __syncthreads();
        // load K1,K2 tiles (tf32)
        for (int i = tid; i < 4096; i += 256) {
            int bq = i >> 11;
            int r  = (i >> 5) & 63;
            int c4 = (i & 31) << 2;
            const float* src = (bq ? g_k2 : g_k1) + ((size_t)bh * Tt + kb * 64 + r) * HH + c4;
            float4 v = *(const float4*)src;
            uint4 u;
            u.x = f2tf32(v.x); u.y = f2tf32(v.y); u.z = f2tf32(v.z); u.w = f2tf32(v.w);
            *(uint4*)&k_s[bq * 8448 + r * 132 + c4] = u;
        }
        // load V tile straight from g_V (tf32)
        for (int i = tid; i < 4096; i += 256) {
            int r  = i >> 6;
            int c4 = (i & 63) << 2;
            float4 v = *(const float4*)(vsrc + (size_t)(kb * 64 + r) * Cc + c4);
            uint4 u;
            u.x = f2tf32(v.x); u.y = f2tf32(v.y); u.z = f2tf32(v.z); u.w = f2tf32(v.w);
            *(uint4*)&v_s[r * 264 + c4] = u;
        }
        __syncthreads();

        // ---- S = Q K^T (16 rows x 64 keys, own branch) ----
        float sc[8][4];
#pragma unroll
        for (int nt = 0; nt < 8; nt++) { sc[nt][0]=0.f; sc[nt][1]=0.f; sc[nt][2]=0.f; sc[nt][3]=0.f; }
        {
            const unsigned* qb = q_s + br * 8448 + mrow * 132;
            const unsigned* kk = k_s + br * 8448;
#pragma unroll
            for (int ks = 0; ks < 16; ks++) {
                int col = 8 * ks + t;
                unsigned a[4];
                a[0] = qb[g * 132 + col];
                a[1] = qb[(g + 8) * 132 + col];
                a[2] = qb[g * 132 + col + 4];
                a[3] = qb[(g + 8) * 132 + col + 4];
#pragma unroll
                for (int nt = 0; nt < 8; nt++) {
                    unsigned bb[2];
                    bb[0] = kk[(8 * nt + g) * 132 + col];
                    bb[1] = kk[(8 * nt + g) * 132 + col + 4];
                    mma_tf32(sc[nt], a, bb);
                }
            }
        }

        // ---- causal mask (diagonal tile only) ----
        if (kb == qt) {
            int row0 = q0 + mrow + g;
            int row1 = row0 + 8;
#pragma unroll
            for (int nt = 0; nt < 8; nt++) {
                int kc = kb * 64 + 8 * nt + 2 * t;
                if (kc     > row0) sc[nt][0] = -1e30f;
                if (kc + 1 > row0) sc[nt][1] = -1e30f;
                if (kc     > row1) sc[nt][2] = -1e30f;
                if (kc + 1 > row1) sc[nt][3] = -1e30f;
            }
        }

        // ---- online softmax (base-2 domain), warp-local ----
        float mx0 = -1e30f, mx1 = -1e30f;
#pragma unroll
        for (int nt = 0; nt < 8; nt++) {
            mx0 = fmaxf(mx0, fmaxf(sc[nt][0], sc[nt][1]));
            mx1 = fmaxf(mx1, fmaxf(sc[nt][2], sc[nt][3]));
        }
        mx0 = fmaxf(mx0, __shfl_xor_sync(0xffffffffu, mx0, 1));
        mx0 = fmaxf(mx0, __shfl_xor_sync(0xffffffffu, mx0, 2));
        mx1 = fmaxf(mx1, __shfl_xor_sync(0xffffffffu, mx1, 1));
        mx1 = fmaxf(mx1, __shfl_xor_sync(0xffffffffu, mx1, 2));
        float nm0 = fmaxf(m0, mx0), nm1 = fmaxf(m1, mx1);
        float c0 = exp2f(m0 - nm0), c1 = exp2f(m1 - nm1);
        m0 = nm0; m1 = nm1;
        float s0 = 0.f, s1 = 0.f;
#pragma unroll
        for (int nt = 0; nt < 8; nt++) {
            sc[nt][0] = exp2f(sc[nt][0] - m0);
            sc[nt][1] = exp2f(sc[nt][1] - m0);
            sc[nt][2] = exp2f(sc[nt][2] - m1);
            sc[nt][3] = exp2f(sc[nt][3] - m1);
            s0 += sc[nt][0] + sc[nt][1];
            s1 += sc[nt][2] + sc[nt][3];
        }
        s0 += __shfl_xor_sync(0xffffffffu, s0, 1);
        s0 += __shfl_xor_sync(0xffffffffu, s0, 2);
        s1 += __shfl_xor_sync(0xffffffffu, s1, 1);
        s1 += __shfl_xor_sync(0xffffffffu, s1, 2);
        l0 = l0 * c0 + s0;
        l1 = l1 * c1 + s1;
        if (c0 != 1.f || c1 != 1.f) {
#pragma unroll
            for (int nt = 0; nt < 32; nt++) {
                oa[nt][0] *= c0; oa[nt][1] *= c0;
                oa[nt][2] *= c1; oa[nt][3] *= c1;
            }
        }

        // ---- P -> tf32 (rna, unbiased) ----
#pragma unroll
        for (int nt = 0; nt < 8; nt++) {
            sc[nt][0] = __uint_as_float(f2tf32(sc[nt][0]));
            sc[nt][1] = __uint_as_float(f2tf32(sc[nt][1]));
            sc[nt][2] = __uint_as_float(f2tf32(sc[nt][2]));
            sc[nt][3] = __uint_as_float(f2tf32(sc[nt][3]));
        }

        // ---- O += P V : C-frag -> A-frag via intra-group shfl ----
        const int srcA = (lane & ~3) | (t >> 1);
        const int srcB = (lane & ~3) | (((t >> 1) + 2) & 3);
#pragma unroll
        for (int kp = 0; kp < 8; kp++) {
            float x0  = __shfl_sync(0xffffffffu, sc[kp][0], srcA);
            float x1  = __shfl_sync(0xffffffffu, sc[kp][1], srcA);
            float y0  = __shfl_sync(0xffffffffu, sc[kp][2], srcA);
            float y1  = __shfl_sync(0xffffffffu, sc[kp][3], srcA);
            float x0b = __shfl_sync(0xffffffffu, sc[kp][0], srcB);
            float x1b = __shfl_sync(0xffffffffu, sc[kp][1], srcB);
            float y0b = __shfl_sync(0xffffffffu, sc[kp][2], srcB);
            float y1b = __shfl_sync(0xffffffffu, sc[kp][3], srcB);
            unsigned pa[4];
            pa[0] = __float_as_uint((t & 1) ? x1  : x0);
            pa[1] = __float_as_uint((t & 1) ? y1  : y0);
            pa[2] = __float_as_uint((t & 1) ? x1b : x0b);
            pa[3] = __float_as_uint((t & 1) ? y1b : y0b);
            const unsigned* v0r = v_s + (8 * kp + t) * 264;
            const unsigned* v1r = v_s + (8 * kp + t + 4) * 264;
#pragma unroll
            for (int nt = 0; nt < 32; nt++) {
                unsigned vb[2];
                vb[0] = v0r[8 * nt + g];
                vb[1] = v1r[8 * nt + g];
                mma_tf32(oa[nt], pa, vb);
            }
        }
    }

    // ---- combine branches: y = O1/l1 - lam * O2/l2 ----
    __syncthreads();
    float* ex = smf;                       // reuse Q region
    float lam = g_lam;
    if (br == 0) {
        float r0 = 1.f / l0, r1 = 1.f / l1;
        float* eb = ex + strip * 4096;
#pragma unroll
        for (int nt = 0; nt < 32; nt++) {
            eb[(nt * 4 + 0) * 32 + lane] = oa[nt][0] * r0;
            eb[(nt * 4 + 1) * 32 + lane] = oa[nt][1] * r0;
            eb[(nt * 4 + 2) * 32 + lane] = oa[nt][2] * r1;
            eb[(nt * 4 + 3) * 32 + lane] = oa[nt][3] * r1;
        }
    }
    __syncthreads();
    if (br == 1) {
        float r0 = lam / l0, r1 = lam / l1;
        const float* eb = ex + strip * 4096;
        int row0 = q0 + mrow + g;
        float* y0p = g_y + ((size_t)(b_ * Tt) + row0) * Cc + h_ * HD;
        float* y1p = y0p + (size_t)8 * Cc;
#pragma unroll
        for (int nt = 0; nt < 32; nt++) {
            int col = 8 * nt + 2 * t;
            float2 o0, o1;
            o0.x = eb[(nt * 4 + 0) * 32 + lane] - oa[nt][0] * r0;
            o0.y = eb[(nt * 4 + 1) * 32 + lane] - oa[nt][1] * r0;
            o1.x = eb[(nt * 4 + 2) * 32 + lane] - oa[nt][2] * r1;
            o1.y = eb[(nt * 4 + 3) * 32 + lane] - oa[nt][3] * r1;
            *(float2*)(y0p + col) = o0;
            *(float2*)(y1p + col) = o1;
        }
    }
}

// ---------------- launcher ----------------
extern "C" void kernel_launch(void* const* d_in, const int* in_sizes, int n_in,
                              void* d_out, int out_size)
{
    const float* x   = (const float*)d_in[0];
    const float* wq  = (const float*)d_in[1];
    const float* wk  = (const float*)d_in[2];
    const float* wv  = (const float*)d_in[3];
    const float* wo  = (const float*)d_in[4];
    const float* lq1 = (const float*)d_in[5];
    const float* lk1 = (const float*)d_in[6];
    const float* lq2 = (const float*)d_in[7];
    const float* lk2 = (const float*)d_in[8];
    float* out = (float*)d_out;

    void* pY;
    cudaGetSymbolAddress(&pY, g_y);

    dim3 gg(Cc / 128, (Bsz * Tt) / 128);
    tgemm_qkv<<<dim3(Cc / 128, (Bsz * Tt) / 128, 3), 256>>>(x, wq, wk, wv);
    lam_kernel<<<1, 256>>>(lq1, lk1, lq2, lk2);
    prep_kernel<<<Bsz * Tt * NH, 128>>>();

    int smem = 3 * 16896 * 4;   // 202752 B
    cudaFuncSetAttribute(attn_tc, cudaFuncAttributeMaxDynamicSharedMemorySize, smem);
    attn_tc<<<dim3(Bsz * NH, Tt / 64), 256, smem>>>();

    tgemm_nt<<<gg, 256>>>((const float*)pY, wo, out, Cc, Cc, 0.8f);
}

// round 7
// speedup vs baseline: 4.9022x; 1.2028x over previous
#include <cuda_runtime.h>
#include <math.h>

#define Bsz 2
#define Tt  2048
#define Cc  2048
#define NH  8
#define HD  256
#define HH  128
#define SCALE 0.08838834764831845f   // 1/sqrt(128)

// ---------------- scratch (device globals: sanctioned, no alloc) ----------------
__device__ float g_Q [Bsz*Tt*Cc];
__device__ float g_K [Bsz*Tt*Cc];
__device__ float g_V [Bsz*Tt*Cc];
__device__ float g_q1[Bsz*NH*Tt*HH];
__device__ float g_q2[Bsz*NH*Tt*HH];
__device__ float g_k1[Bsz*NH*Tt*HH];
__device__ float g_k2[Bsz*NH*Tt*HH];
__device__ float g_y [Bsz*Tt*Cc];
__device__ float g_X [Bsz*Tt*Cc];    // tf32-rounded x
__device__ float g_Wq[Cc*Cc];        // tf32-rounded weights
__device__ float g_Wk[Cc*Cc];
__device__ float g_Wv[Cc*Cc];
__device__ float g_Wo[Cc*Cc];
__device__ float g_lam;

// ---------------- helpers ----------------
__device__ __forceinline__ unsigned f2tf32(float x) {
    unsigned r;
    asm("cvt.rna.tf32.f32 %0, %1;" : "=r"(r) : "f"(x));
    return r;
}

__device__ __forceinline__ void mma_tf32(float* d, const unsigned* a, const unsigned* b) {
    asm volatile(
        "mma.sync.aligned.m16n8k8.row.col.f32.tf32.tf32.f32 "
        "{%0,%1,%2,%3}, {%4,%5,%6,%7}, {%8,%9}, {%0,%1,%2,%3};"
        : "+f"(d[0]), "+f"(d[1]), "+f"(d[2]), "+f"(d[3])
        : "r"(a[0]), "r"(a[1]), "r"(a[2]), "r"(a[3]), "r"(b[0]), "r"(b[1]));
}

__device__ __forceinline__ void cp_async16(unsigned dst, const void* src) {
    asm volatile("cp.async.cg.shared.global [%0], [%1], 16;" :: "r"(dst), "l"(src));
}

// ---------------- tf32 pre-rounding pass ----------------
// grid (4096, 1, 6): z0,z1 = halves of x; z2..5 = wq,wk,wv,wo. 4M elems each.
__global__ __launch_bounds__(256)
void cvt_kernel(const float* __restrict__ x,  const float* __restrict__ wq,
                const float* __restrict__ wk, const float* __restrict__ wv,
                const float* __restrict__ wo)
{
    const size_t NSEG = (size_t)Cc * Cc;   // 4,194,304
    int z = blockIdx.z;
    const float* src;
    float* dst;
    if      (z == 0) { src = x;           dst = g_X; }
    else if (z == 1) { src = x + NSEG;    dst = g_X + NSEG; }
    else if (z == 2) { src = wq;          dst = g_Wq; }
    else if (z == 3) { src = wk;          dst = g_Wk; }
    else if (z == 4) { src = wv;          dst = g_Wv; }
    else             { src = wo;          dst = g_Wo; }
    size_t i = ((size_t)blockIdx.x * 256 + threadIdx.x) * 4;
    float4 v = *(const float4*)(src + i);
    uint4 u;
    u.x = f2tf32(v.x); u.y = f2tf32(v.y); u.z = f2tf32(v.z); u.w = f2tf32(v.w);
    *(uint4*)(dst + i) = u;
}

// ---------------- TF32 GEMM, cp.async double-buffered ----------------
// C[M,N] = alpha * A[M,K] @ B[N,K]^T. Inputs MUST be pre-rounded to tf32.
// block 128x128x32, 8 warps (2x4), warp 64x32, row-major smem pitch 36 words.
#define RPAD 36
#define STG_W 9216   // words per stage: (A 128*36 + B 128*36) = 4608 + 4608

__device__ __forceinline__
void tgemm_body(const float* __restrict__ A, const float* __restrict__ B,
                float* __restrict__ C, int N, int K, float alpha)
{
    extern __shared__ float smem[];

    const int tid  = threadIdx.x;
    const int wid  = tid >> 5;
    const int lane = tid & 31;
    const int wm   = (wid & 1) * 64;
    const int wn   = (wid >> 1) * 32;
    const int r    = lane >> 2;
    const int c    = lane & 3;
    const int m0   = blockIdx.y * 128;
    const int n0   = blockIdx.x * 128;
    const int ar   = tid >> 3;          // 0..31
    const int ac   = (tid & 7) * 4;     // 0..28

    unsigned sb;
    asm("{.reg .u64 t; cvta.to.shared.u64 t, %1; cvt.u32.u64 %0, t;}"
        : "=r"(sb) : "l"(smem));

    const float* Ap = A + (size_t)(m0 + ar) * K + ac;
    const float* Bp = B + (size_t)(n0 + ar) * K + ac;
    const unsigned daA = sb + (unsigned)(ar * RPAD + ac) * 4;
    const unsigned daB = daA + 4608u * 4;

    float acc[4][4][4];
#pragma unroll
    for (int i = 0; i < 4; i++)
#pragma unroll
        for (int j = 0; j < 4; j++)
#pragma unroll
            for (int e = 0; e < 4; e++) acc[i][j][e] = 0.f;

    // prefetch tile 0 into stage 0
#pragma unroll
    for (int i = 0; i < 4; i++) {
        cp_async16(daA + i * (32 * RPAD * 4), Ap + (size_t)(32 * i) * K);
        cp_async16(daB + i * (32 * RPAD * 4), Bp + (size_t)(32 * i) * K);
    }
    asm volatile("cp.async.commit_group;");

    const int nit = K >> 5;
    for (int it = 0; it < nit; ++it) {
        const int cur = it & 1;
        if (it + 1 < nit) {
            const unsigned off = (unsigned)((cur ^ 1) * STG_W * 4);
            const int k0 = (it + 1) << 5;
#pragma unroll
            for (int i = 0; i < 4; i++) {
                cp_async16(daA + off + i * (32 * RPAD * 4), Ap + (size_t)(32 * i) * K + k0);
                cp_async16(daB + off + i * (32 * RPAD * 4), Bp + (size_t)(32 * i) * K + k0);
            }
        }
        asm volatile("cp.async.commit_group;");
        asm volatile("cp.async.wait_group 1;");
        __syncthreads();

        const unsigned* As = (const unsigned*)smem + cur * STG_W;
        const unsigned* Bs = As + 4608;
#pragma unroll
        for (int ks = 0; ks < 4; ks++) {
            unsigned af[4][4], bf[4][2];
#pragma unroll
            for (int mi = 0; mi < 4; mi++) {
                const unsigned* ap = As + (wm + 16 * mi) * RPAD + 8 * ks + c;
                af[mi][0] = ap[r * RPAD];
                af[mi][1] = ap[(r + 8) * RPAD];
                af[mi][2] = ap[r * RPAD + 4];
                af[mi][3] = ap[(r + 8) * RPAD + 4];
            }
#pragma unroll
            for (int nj = 0; nj < 4; nj++) {
                const unsigned* bp = Bs + (wn + 8 * nj) * RPAD + 8 * ks + c;
                bf[nj][0] = bp[r * RPAD];
                bf[nj][1] = bp[r * RPAD + 4];
            }
#pragma unroll
            for (int mi = 0; mi < 4; mi++)
#pragma unroll
                for (int nj = 0; nj < 4; nj++)
                    mma_tf32(acc[mi][nj], af[mi], bf[nj]);
        }
        __syncthreads();
    }

#pragma unroll
    for (int mi = 0; mi < 4; mi++) {
#pragma unroll
        for (int nj = 0; nj < 4; nj++) {
            int row = m0 + wm + 16 * mi + r;
            int col = n0 + wn + 8 * nj + 2 * c;
            *(float2*)(C + (size_t)row * N + col) =
                make_float2(alpha * acc[mi][nj][0], alpha * acc[mi][nj][1]);
            *(float2*)(C + (size_t)(row + 8) * N + col) =
                make_float2(alpha * acc[mi][nj][2], alpha * acc[mi][nj][3]);
        }
    }
}

// fused Q/K/V projection: blockIdx.z selects weight + destination
__global__ __launch_bounds__(256, 2)
void tgemm_qkv()
{
    const float* B = (blockIdx.z == 0) ? g_Wq : (blockIdx.z == 1) ? g_Wk : g_Wv;
    float* C = (blockIdx.z == 0) ? g_Q : (blockIdx.z == 1) ? g_K : g_V;
    tgemm_body(g_X, B, C, Cc, Cc, 1.0f);
}

__global__ __launch_bounds__(256, 2)
void tgemm_wo(float* __restrict__ out)
{
    tgemm_body(g_y, g_Wo, out, Cc, Cc, 0.8f);
}

// ---------------- lambda scalar ----------------
__global__ void lam_kernel(const float* __restrict__ lq1, const float* __restrict__ lk1,
                           const float* __restrict__ lq2, const float* __restrict__ lk2)
{
    int d = threadIdx.x;             // 256 threads
    float p1 = lq1[d] * lk1[d];
    float p2 = lq2[d] * lk2[d];
#pragma unroll
    for (int o = 16; o; o >>= 1) {
        p1 += __shfl_xor_sync(0xffffffffu, p1, o);
        p2 += __shfl_xor_sync(0xffffffffu, p2, o);
    }
    __shared__ float w1[8], w2[8];
    if ((d & 31) == 0) { w1[d >> 5] = p1; w2[d >> 5] = p2; }
    __syncthreads();
    if (d == 0) {
        float s1 = 0.f, s2 = 0.f;
        for (int i = 0; i < 8; i++) { s1 += w1[i]; s2 += w2[i]; }
        g_lam = expf(s1) - expf(s2) + 0.2f;
    }
}

// ---------------- rmsnorm + (head-indexed) rotary + transpose, warp-level ----
__global__ __launch_bounds__(128)
void prep_kernel()
{
    int idx = blockIdx.x;            // (b*T + t)*NH + h
    int h = idx & 7;
    int t = (idx >> 3) & 2047;
    int b = idx >> 14;
    int tid  = threadIdx.x;
    int w    = tid >> 5;
    int lane = tid & 31;

    size_t inb  = ((size_t)(b * Tt) + t) * Cc + h * HD;
    size_t outb = ((size_t)(b * NH + h) * Tt + t) * HH;

    const float* src;
    float* dst;
    if      (w == 0) { src = g_Q + inb;      dst = g_q1 + outb; }
    else if (w == 1) { src = g_Q + inb + HH; dst = g_q2 + outb; }
    else if (w == 2) { src = g_K + inb;      dst = g_k1 + outb; }
    else             { src = g_K + inb + HH; dst = g_k2 + outb; }

    float4 v = ((const float4*)src)[lane];
    float sq = v.x*v.x + v.y*v.y + v.z*v.z + v.w*v.w;
#pragma unroll
    for (int o = 16; o; o >>= 1) sq += __shfl_xor_sync(0xffffffffu, sq, o);
    float rn = rsqrtf(sq * (1.0f / 128.0f) + 1.1920929e-07f);

    float4 p;
    p.x = __shfl_xor_sync(0xffffffffu, v.x, 16);
    p.y = __shfl_xor_sync(0xffffffffu, v.y, 16);
    p.z = __shfl_xor_sync(0xffffffffu, v.z, 16);
    p.w = __shfl_xor_sync(0xffffffffu, v.w, 16);

    bool first = lane < 16;
    int j0 = first ? 4 * lane : 4 * (lane - 16);
    float vv[4] = {v.x, v.y, v.z, v.w};
    float pp[4] = {p.x, p.y, p.z, p.w};
    float out[4];
#pragma unroll
    for (int i = 0; i < 4; i++) {
        // buggy-rotary angle: position index = head index h
        float ang = (float)h * exp2f(-(float)(j0 + i) * (13.287712379549449f / 64.0f));
        float cj = cosf(ang), sj = sinf(ang);
        float vd = vv[i] * rn, vp = pp[i] * rn;
        out[i] = first ? (vd * cj + vp * sj) : (vd * cj - vp * sj);
    }
    ((float4*)dst)[lane] = make_float4(out[0], out[1], out[2], out[3]);
}

// ---------------- tensor-core dual causal flash attention ----------------
// grid (16 bh, 32 qtiles reversed), 256 thr = 8 warps = 4 M-strips x 2 branches.
__global__ __launch_bounds__(256, 1)
void attn_tc()
{
    extern __shared__ float smf[];
    unsigned* q_s = (unsigned*)smf;        // [2][64][132]
    unsigned* k_s = q_s + 16896;           // [2][64][132]
    unsigned* v_s = k_s + 16896;           // [64][264]

    const int tid   = threadIdx.x;
    const int lane  = tid & 31;
    const int w     = tid >> 5;
    const int g     = lane >> 2;
    const int t     = lane & 3;
    const int br    = w & 1;
    const int strip = w >> 1;
    const int mrow  = strip * 16;
    const int bh    = blockIdx.x;
    const int qt    = (int)gridDim.y - 1 - (int)blockIdx.y;  // big tiles first
    const int q0    = qt * 64;

    const float QSC = SCALE * 1.4426950408889634f;   // fold scale + log2(e)

    // load Q tile (both branches), scaled, tf32
    for (int i = tid; i < 4096; i += 256) {
        int bq = i >> 11;
        int r  = (i >> 5) & 63;
        int c4 = (i & 31) << 2;
        const float* src = (bq ? g_q2 : g_q1) + ((size_t)bh * Tt + q0 + r) * HH + c4;
        float4 v = *(const float4*)src;
        uint4 u;
        u.x = f2tf32(v.x * QSC); u.y = f2tf32(v.y * QSC);
        u.z = f2tf32(v.z * QSC); u.w = f2tf32(v.w * QSC);
        *(uint4*)&q_s[bq * 8448 + r * 132 + c4] = u;
    }

    float oa[32][4];
#pragma unroll
    for (int i = 0; i < 32; i++) { oa[i][0]=0.f; oa[i][1]=0.f; oa[i][2]=0.f; oa[i][3]=0.f; }
    float m0 = -1e30f, m1 = -1e30f, l0 = 0.f, l1 = 0.f;

    const int b_ = bh >> 3, h_ = bh & 7;
    const float* vsrc = g_V + (size_t)(b_ * Tt) * Cc + h_ * HD;

    for (int kb = 0; kb <= qt; kb++) {
        __syncthreads();
        // load K1,K2 tiles (tf32)
        for (int i = tid; i < 4096; i += 256) {
            int bq = i >> 11;
            int r  = (i >> 5) & 63;
            int c4 = (i & 31) << 2;
            const float* src = (bq ? g_k2 : g_k1) + ((size_t)bh * Tt + kb * 64 + r) * HH + c4;
            float4 v = *(const float4*)src;
            uint4 u;
            u.x = f2tf32(v.x); u.y = f2tf32(v.y); u.z = f2tf32(v.z); u.w = f2tf32(v.w);
            *(uint4*)&k_s[bq * 8448 + r * 132 + c4] = u;
        }
        // load V tile straight from g_V (tf32)
        for (int i = tid; i < 4096; i += 256) {
            int r  = i >> 6;
            int c4 = (i & 63) << 2;
            float4 v = *(const float4*)(vsrc + (size_t)(kb * 64 + r) * Cc + c4);
            uint4 u;
            u.x = f2tf32(v.x); u.y = f2tf32(v.y); u.z = f2tf32(v.z); u.w = f2tf32(v.w);
            *(uint4*)&v_s[r * 264 + c4] = u;
        }
        __syncthreads();

        // ---- S = Q K^T (16 rows x 64 keys, own branch) ----
        float sc[8][4];
#pragma unroll
        for (int nt = 0; nt < 8; nt++) { sc[nt][0]=0.f; sc[nt][1]=0.f; sc[nt][2]=0.f; sc[nt][3]=0.f; }
        {
            const unsigned* qb = q_s + br * 8448 + mrow * 132;
            const unsigned* kk = k_s + br * 8448;
#pragma unroll
            for (int ks = 0; ks < 16; ks++) {
                int col = 8 * ks + t;
                unsigned a[4];
                a[0] = qb[g * 132 + col];
                a[1] = qb[(g + 8) * 132 + col];
                a[2] = qb[g * 132 + col + 4];
                a[3] = qb[(g + 8) * 132 + col + 4];
#pragma unroll
                for (int nt = 0; nt < 8; nt++) {
                    unsigned bb[2];
                    bb[0] = kk[(8 * nt + g) * 132 + col];
                    bb[1] = kk[(8 * nt + g) * 132 + col + 4];
                    mma_tf32(sc[nt], a, bb);
                }
            }
        }

        // ---- causal mask (diagonal tile only) ----
        if (kb == qt) {
            int row0 = q0 + mrow + g;
            int row1 = row0 + 8;
#pragma unroll
            for (int nt = 0; nt < 8; nt++) {
                int kc = kb * 64 + 8 * nt + 2 * t;
                if (kc     > row0) sc[nt][0] = -1e30f;
                if (kc + 1 > row0) sc[nt][1] = -1e30f;
                if (kc     > row1) sc[nt][2] = -1e30f;
                if (kc + 1 > row1) sc[nt][3] = -1e30f;
            }
        }

        // ---- online softmax (base-2 domain), warp-local ----
        float mx0 = -1e30f, mx1 = -1e30f;
#pragma unroll
        for (int nt = 0; nt < 8; nt++) {
            mx0 = fmaxf(mx0, fmaxf(sc[nt][0], sc[nt][1]));
            mx1 = fmaxf(mx1, fmaxf(sc[nt][2], sc[nt][3]));
        }
        mx0 = fmaxf(mx0, __shfl_xor_sync(0xffffffffu, mx0, 1));
        mx0 = fmaxf(mx0, __shfl_xor_sync(0xffffffffu, mx0, 2));
        mx1 = fmaxf(mx1, __shfl_xor_sync(0xffffffffu, mx1, 1));
        mx1 = fmaxf(mx1, __shfl_xor_sync(0xffffffffu, mx1, 2));
        float nm0 = fmaxf(m0, mx0), nm1 = fmaxf(m1, mx1);
        float c0 = exp2f(m0 - nm0), c1 = exp2f(m1 - nm1);
        m0 = nm0; m1 = nm1;
        float s0 = 0.f, s1 = 0.f;
#pragma unroll
        for (int nt = 0; nt < 8; nt++) {
            sc[nt][0] = exp2f(sc[nt][0] - m0);
            sc[nt][1] = exp2f(sc[nt][1] - m0);
            sc[nt][2] = exp2f(sc[nt][2] - m1);
            sc[nt][3] = exp2f(sc[nt][3] - m1);
            s0 += sc[nt][0] + sc[nt][1];
            s1 += sc[nt][2] + sc[nt][3];
        }
        s0 += __shfl_xor_sync(0xffffffffu, s0, 1);
        s0 += __shfl_xor_sync(0xffffffffu, s0, 2);
        s1 += __shfl_xor_sync(0xffffffffu, s1, 1);
        s1 += __shfl_xor_sync(0xffffffffu, s1, 2);
        l0 = l0 * c0 + s0;
        l1 = l1 * c1 + s1;
        if (c0 != 1.f || c1 != 1.f) {
#pragma unroll
            for (int nt = 0; nt < 32; nt++) {
                oa[nt][0] *= c0; oa[nt][1] *= c0;
                oa[nt][2] *= c1; oa[nt][3] *= c1;
            }
        }

        // ---- P -> tf32 (rna, unbiased) ----
#pragma unroll
        for (int nt = 0; nt < 8; nt++) {
            sc[nt][0] = __uint_as_float(f2tf32(sc[nt][0]));
            sc[nt][1] = __uint_as_float(f2tf32(sc[nt][1]));
            sc[nt][2] = __uint_as_float(f2tf32(sc[nt][2]));
            sc[nt][3] = __uint_as_float(f2tf32(sc[nt][3]));
        }

        // ---- O += P V : C-frag -> A-frag via intra-group shfl ----
        const int srcA = (lane & ~3) | (t >> 1);
        const int srcB = (lane & ~3) | (((t >> 1) + 2) & 3);
#pragma unroll
        for (int kp = 0; kp < 8; kp++) {
            float x0  = __shfl_sync(0xffffffffu, sc[kp][0], srcA);
            float x1  = __shfl_sync(0xffffffffu, sc[kp][1], srcA);
            float y0  = __shfl_sync(0xffffffffu, sc[kp][2], srcA);
            float y1  = __shfl_sync(0xffffffffu, sc[kp][3], srcA);
            float x0b = __shfl_sync(0xffffffffu, sc[kp][0], srcB);
            float x1b = __shfl_sync(0xffffffffu, sc[kp][1], srcB);
            float y0b = __shfl_sync(0xffffffffu, sc[kp][2], srcB);
            float y1b = __shfl_sync(0xffffffffu, sc[kp][3], srcB);
            unsigned pa[4];
            pa[0] = __float_as_uint((t & 1) ? x1  : x0);
            pa[1] = __float_as_uint((t & 1) ? y1  : y0);
            pa[2] = __float_as_uint((t & 1) ? x1b : x0b);
            pa[3] = __float_as_uint((t & 1) ? y1b : y0b);
            const unsigned* v0r = v_s + (8 * kp + t) * 264;
            const unsigned* v1r = v_s + (8 * kp + t + 4) * 264;
#pragma unroll
            for (int nt = 0; nt < 32; nt++) {
                unsigned vb[2];
                vb[0] = v0r[8 * nt + g];
                vb[1] = v1r[8 * nt + g];
                mma_tf32(oa[nt], pa, vb);
            }
        }
    }

    // ---- combine branches: y = O1/l1 - lam * O2/l2 (stored tf32-rounded) ----
    __syncthreads();
    float* ex = smf;                       // reuse Q region
    float lam = g_lam;
    if (br == 0) {
        float r0 = 1.f / l0, r1 = 1.f / l1;
        float* eb = ex + strip * 4096;
#pragma unroll
        for (int nt = 0; nt < 32; nt++) {
            eb[(nt * 4 + 0) * 32 + lane] = oa[nt][0] * r0;
            eb[(nt * 4 + 1) * 32 + lane] = oa[nt][1] * r0;
            eb[(nt * 4 + 2) * 32 + lane] = oa[nt][2] * r1;
            eb[(nt * 4 + 3) * 32 + lane] = oa[nt][3] * r1;
        }
    }
    __syncthreads();
    if (br == 1) {
        float r0 = lam / l0, r1 = lam / l1;
        const float* eb = ex + strip * 4096;
        int row0 = q0 + mrow + g;
        float* y0p = g_y + ((size_t)(b_ * Tt) + row0) * Cc + h_ * HD;
        float* y1p = y0p + (size_t)8 * Cc;
#pragma unroll
        for (int nt = 0; nt < 32; nt++) {
            int col = 8 * nt + 2 * t;
            float2 o0, o1;
            o0.x = __uint_as_float(f2tf32(eb[(nt * 4 + 0) * 32 + lane] - oa[nt][0] * r0));
            o0.y = __uint_as_float(f2tf32(eb[(nt * 4 + 1) * 32 + lane] - oa[nt][1] * r0));
            o1.x = __uint_as_float(f2tf32(eb[(nt * 4 + 2) * 32 + lane] - oa[nt][2] * r1));
            o1.y = __uint_as_float(f2tf32(eb[(nt * 4 + 3) * 32 + lane] - oa[nt][3] * r1));
            *(float2*)(y0p + col) = o0;
            *(float2*)(y1p + col) = o1;
        }
    }
}

// ---------------- launcher ----------------
extern "C" void kernel_launch(void* const* d_in, const int* in_sizes, int n_in,
                              void* d_out, int out_size)
{
    const float* x   = (const float*)d_in[0];
    const float* wq  = (const float*)d_in[1];
    const float* wk  = (const float*)d_in[2];
    const float* wv  = (const float*)d_in[3];
    const float* wo  = (const float*)d_in[4];
    const float* lq1 = (const float*)d_in[5];
    const float* lk1 = (const float*)d_in[6];
    const float* lq2 = (const float*)d_in[7];
    const float* lk2 = (const float*)d_in[8];
    float* out = (float*)d_out;

    const int gsm = STG_W * 2 * 4;   // 73728 B
    cudaFuncSetAttribute(tgemm_qkv, cudaFuncAttributeMaxDynamicSharedMemorySize, gsm);
    cudaFuncSetAttribute(tgemm_wo,  cudaFuncAttributeMaxDynamicSharedMemorySize, gsm);

    cvt_kernel<<<dim3(4096, 1, 6), 256>>>(x, wq, wk, wv, wo);
    tgemm_qkv<<<dim3(Cc / 128, (Bsz * Tt) / 128, 3), 256, gsm>>>();
    lam_kernel<<<1, 256>>>(lq1, lk1, lq2, lk2);
    prep_kernel<<<Bsz * Tt * NH, 128>>>();

    int smem = 3 * 16896 * 4;   // 202752 B
    cudaFuncSetAttribute(attn_tc, cudaFuncAttributeMaxDynamicSharedMemorySize, smem);
    attn_tc<<<dim3(Bsz * NH, Tt / 64), 256, smem>>>();

    tgemm_wo<<<dim3(Cc / 128, (Bsz * Tt) / 128), 256, gsm>>>(out);
}

// round 8
// speedup vs baseline: 5.4768x; 1.1172x over previous
#include <cuda_runtime.h>
#include <math.h>

#define Bsz 2
#define Tt  2048
#define Cc  2048
#define NH  8
#define HD  256
#define HH  128
#define SCALE 0.08838834764831845f   // 1/sqrt(128)

// ---------------- scratch (device globals: sanctioned, no alloc) ----------------
__device__ float g_Q [Bsz*Tt*Cc];
__device__ float g_K [Bsz*Tt*Cc];
__device__ float g_V [Bsz*Tt*Cc];     // stored tf32-rounded by GEMM epilogue
__device__ float g_q1[Bsz*NH*Tt*HH];  // tf32-rounded, pre-scaled by SCALE*log2e
__device__ float g_q2[Bsz*NH*Tt*HH];
__device__ float g_k1[Bsz*NH*Tt*HH];  // tf32-rounded
__device__ float g_k2[Bsz*NH*Tt*HH];
__device__ float g_y [Bsz*Tt*Cc];     // tf32-rounded by attn epilogue
__device__ float g_X [Bsz*Tt*Cc];     // tf32-rounded x
__device__ float g_Wq[Cc*Cc];         // tf32-rounded weights
__device__ float g_Wk[Cc*Cc];
__device__ float g_Wv[Cc*Cc];
__device__ float g_Wo[Cc*Cc];
__device__ float g_lam;

// ---------------- helpers ----------------
__device__ __forceinline__ unsigned f2tf32(float x) {
    unsigned r;
    asm("cvt.rna.tf32.f32 %0, %1;" : "=r"(r) : "f"(x));
    return r;
}

__device__ __forceinline__ void mma_tf32(float* d, const unsigned* a, const unsigned* b) {
    asm volatile(
        "mma.sync.aligned.m16n8k8.row.col.f32.tf32.tf32.f32 "
        "{%0,%1,%2,%3}, {%4,%5,%6,%7}, {%8,%9}, {%0,%1,%2,%3};"
        : "+f"(d[0]), "+f"(d[1]), "+f"(d[2]), "+f"(d[3])
        : "r"(a[0]), "r"(a[1]), "r"(a[2]), "r"(a[3]), "r"(b[0]), "r"(b[1]));
}

__device__ __forceinline__ void cp_async16(unsigned dst, const void* src) {
    asm volatile("cp.async.cg.shared.global [%0], [%1], 16;" :: "r"(dst), "l"(src));
}
__device__ __forceinline__ void cp_commit()  { asm volatile("cp.async.commit_group;"); }
__device__ __forceinline__ unsigned smem_u32(const void* p) {
    unsigned r;
    asm("{.reg .u64 t; cvta.to.shared.u64 t, %1; cvt.u32.u64 %0, t;}" : "=r"(r) : "l"(p));
    return r;
}

// ---------------- tf32 pre-rounding pass ----------------
__global__ __launch_bounds__(256)
void cvt_kernel(const float* __restrict__ x,  const float* __restrict__ wq,
                const float* __restrict__ wk, const float* __restrict__ wv,
                const float* __restrict__ wo)
{
    const size_t NSEG = (size_t)Cc * Cc;
    int z = blockIdx.z;
    const float* src;
    float* dst;
    if      (z == 0) { src = x;        dst = g_X; }
    else if (z == 1) { src = x + NSEG; dst = g_X + NSEG; }
    else if (z == 2) { src = wq;       dst = g_Wq; }
    else if (z == 3) { src = wk;       dst = g_Wk; }
    else if (z == 4) { src = wv;       dst = g_Wv; }
    else             { src = wo;       dst = g_Wo; }
    size_t i = ((size_t)blockIdx.x * 256 + threadIdx.x) * 4;
    float4 v = *(const float4*)(src + i);
    uint4 u;
    u.x = f2tf32(v.x); u.y = f2tf32(v.y); u.z = f2tf32(v.z); u.w = f2tf32(v.w);
    *(uint4*)(dst + i) = u;
}

// ---------------- TF32 GEMM, cp.async triple-buffered ----------------
// C[M,N] = alpha * A[M,K] @ B[N,K]^T. Inputs MUST be pre-rounded to tf32.
#define RPAD 36
#define STG_W 9216   // words per stage

__device__ __forceinline__
void tgemm_body(const float* __restrict__ A, const float* __restrict__ B,
                float* __restrict__ C, int N, int K, float alpha, bool rnd)
{
    extern __shared__ float smem[];

    const int tid  = threadIdx.x;
    const int wid  = tid >> 5;
    const int lane = tid & 31;
    const int wm   = (wid & 1) * 64;
    const int wn   = (wid >> 1) * 32;
    const int r    = lane >> 2;
    const int c    = lane & 3;
    const int m0   = blockIdx.y * 128;
    const int n0   = blockIdx.x * 128;
    const int ar   = tid >> 3;
    const int ac   = (tid & 7) * 4;

    const unsigned sb = smem_u32(smem);
    const float* Ap = A + (size_t)(m0 + ar) * K + ac;
    const float* Bp = B + (size_t)(n0 + ar) * K + ac;
    const unsigned daA = sb + (unsigned)(ar * RPAD + ac) * 4;
    const unsigned daB = daA + 4608u * 4;

    float acc[4][4][4];
#pragma unroll
    for (int i = 0; i < 4; i++)
#pragma unroll
        for (int j = 0; j < 4; j++)
#pragma unroll
            for (int e = 0; e < 4; e++) acc[i][j][e] = 0.f;

    const int nit = K >> 5;
    // prefetch tiles 0,1 into stages 0,1
#pragma unroll
    for (int pf = 0; pf < 2; pf++) {
        const unsigned off = (unsigned)(pf * STG_W * 4);
        const int k0 = pf << 5;
#pragma unroll
        for (int i = 0; i < 4; i++) {
            cp_async16(daA + off + i * (32 * RPAD * 4), Ap + (size_t)(32 * i) * K + k0);
            cp_async16(daB + off + i * (32 * RPAD * 4), Bp + (size_t)(32 * i) * K + k0);
        }
        cp_commit();
    }

    int cur = 0, nxt = 2;
    for (int it = 0; it < nit; ++it) {
        if (it + 2 < nit) {
            const unsigned off = (unsigned)(nxt * STG_W * 4);
            const int k0 = (it + 2) << 5;
#pragma unroll
            for (int i = 0; i < 4; i++) {
                cp_async16(daA + off + i * (32 * RPAD * 4), Ap + (size_t)(32 * i) * K + k0);
                cp_async16(daB + off + i * (32 * RPAD * 4), Bp + (size_t)(32 * i) * K + k0);
            }
        }
        cp_commit();
        asm volatile("cp.async.wait_group 2;");
        __syncthreads();

        const unsigned* As = (const unsigned*)smem + cur * STG_W;
        const unsigned* Bs = As + 4608;
#pragma unroll
        for (int ks = 0; ks < 4; ks++) {
            unsigned af[4][4], bf[4][2];
#pragma unroll
            for (int mi = 0; mi < 4; mi++) {
                const unsigned* ap = As + (wm + 16 * mi) * RPAD + 8 * ks + c;
                af[mi][0] = ap[r * RPAD];
                af[mi][1] = ap[(r + 8) * RPAD];
                af[mi][2] = ap[r * RPAD + 4];
                af[mi][3] = ap[(r + 8) * RPAD + 4];
            }
#pragma unroll
            for (int nj = 0; nj < 4; nj++) {
                const unsigned* bp = Bs + (wn + 8 * nj) * RPAD + 8 * ks + c;
                bf[nj][0] = bp[r * RPAD];
                bf[nj][1] = bp[r * RPAD + 4];
            }
#pragma unroll
            for (int mi = 0; mi < 4; mi++)
#pragma unroll
                for (int nj = 0; nj < 4; nj++)
                    mma_tf32(acc[mi][nj], af[mi], bf[nj]);
        }
        __syncthreads();
        cur = (cur == 2) ? 0 : cur + 1;
        nxt = (nxt == 2) ? 0 : nxt + 1;
    }

#pragma unroll
    for (int mi = 0; mi < 4; mi++) {
#pragma unroll
        for (int nj = 0; nj < 4; nj++) {
            int row = m0 + wm + 16 * mi + r;
            int col = n0 + wn + 8 * nj + 2 * c;
            float v0 = alpha * acc[mi][nj][0], v1 = alpha * acc[mi][nj][1];
            float v2 = alpha * acc[mi][nj][2], v3 = alpha * acc[mi][nj][3];
            if (rnd) {
                v0 = __uint_as_float(f2tf32(v0)); v1 = __uint_as_float(f2tf32(v1));
                v2 = __uint_as_float(f2tf32(v2)); v3 = __uint_as_float(f2tf32(v3));
            }
            *(float2*)(C + (size_t)row * N + col)       = make_float2(v0, v1);
            *(float2*)(C + (size_t)(row + 8) * N + col) = make_float2(v2, v3);
        }
    }
}

__global__ __launch_bounds__(256, 2)
void tgemm_qkv()
{
    const float* B = (blockIdx.z == 0) ? g_Wq : (blockIdx.z == 1) ? g_Wk : g_Wv;
    float* C = (blockIdx.z == 0) ? g_Q : (blockIdx.z == 1) ? g_K : g_V;
    tgemm_body(g_X, B, C, Cc, Cc, 1.0f, blockIdx.z == 2);  // V pre-rounded for attn
}

__global__ __launch_bounds__(256, 2)
void tgemm_wo(float* __restrict__ out)
{
    tgemm_body(g_y, g_Wo, out, Cc, Cc, 0.8f, false);
}

// ---------------- lambda scalar ----------------
__global__ void lam_kernel(const float* __restrict__ lq1, const float* __restrict__ lk1,
                           const float* __restrict__ lq2, const float* __restrict__ lk2)
{
    int d = threadIdx.x;
    float p1 = lq1[d] * lk1[d];
    float p2 = lq2[d] * lk2[d];
#pragma unroll
    for (int o = 16; o; o >>= 1) {
        p1 += __shfl_xor_sync(0xffffffffu, p1, o);
        p2 += __shfl_xor_sync(0xffffffffu, p2, o);
    }
    __shared__ float w1[8], w2[8];
    if ((d & 31) == 0) { w1[d >> 5] = p1; w2[d >> 5] = p2; }
    __syncthreads();
    if (d == 0) {
        float s1 = 0.f, s2 = 0.f;
        for (int i = 0; i < 8; i++) { s1 += w1[i]; s2 += w2[i]; }
        g_lam = expf(s1) - expf(s2) + 0.2f;
    }
}

// ---------------- rmsnorm + (head-indexed) rotary, outputs tf32-rounded ----
__global__ __launch_bounds__(128)
void prep_kernel()
{
    int idx = blockIdx.x;            // (b*T + t)*NH + h
    int h = idx & 7;
    int t = (idx >> 3) & 2047;
    int b = idx >> 14;
    int tid  = threadIdx.x;
    int w    = tid >> 5;
    int lane = tid & 31;

    size_t inb  = ((size_t)(b * Tt) + t) * Cc + h * HD;
    size_t outb = ((size_t)(b * NH + h) * Tt + t) * HH;

    const float* src;
    float* dst;
    if      (w == 0) { src = g_Q + inb;      dst = g_q1 + outb; }
    else if (w == 1) { src = g_Q + inb + HH; dst = g_q2 + outb; }
    else if (w == 2) { src = g_K + inb;      dst = g_k1 + outb; }
    else             { src = g_K + inb + HH; dst = g_k2 + outb; }

    const float osc = (w < 2) ? (SCALE * 1.4426950408889634f) : 1.0f;

    float4 v = ((const float4*)src)[lane];
    float sq = v.x*v.x + v.y*v.y + v.z*v.z + v.w*v.w;
#pragma unroll
    for (int o = 16; o; o >>= 1) sq += __shfl_xor_sync(0xffffffffu, sq, o);
    float rn = rsqrtf(sq * (1.0f / 128.0f) + 1.1920929e-07f) * osc;

    float4 p;
    p.x = __shfl_xor_sync(0xffffffffu, v.x, 16);
    p.y = __shfl_xor_sync(0xffffffffu, v.y, 16);
    p.z = __shfl_xor_sync(0xffffffffu, v.z, 16);
    p.w = __shfl_xor_sync(0xffffffffu, v.w, 16);

    bool first = lane < 16;
    int j0 = first ? 4 * lane : 4 * (lane - 16);
    float vv[4] = {v.x, v.y, v.z, v.w};
    float pp[4] = {p.x, p.y, p.z, p.w};
    unsigned out[4];
#pragma unroll
    for (int i = 0; i < 4; i++) {
        // buggy-rotary angle: position index = head index h
        float ang = (float)h * exp2f(-(float)(j0 + i) * (13.287712379549449f / 64.0f));
        float cj = cosf(ang), sj = sinf(ang);
        float vd = vv[i] * rn, vp = pp[i] * rn;
        out[i] = f2tf32(first ? (vd * cj + vp * sj) : (vd * cj - vp * sj));
    }
    ((uint4*)dst)[lane] = make_uint4(out[0], out[1], out[2], out[3]);
}

// ---------------- tensor-core dual causal flash attention ----------------
// grid (16 bh, 32 qtiles reversed), 256 thr = 8 warps = 4 M-strips x 2 branches.
// 32-key tiles, double-buffered cp.async (inputs pre-rounded tf32, no cvt).
__global__ __launch_bounds__(256, 1)
void attn_tc()
{
    extern __shared__ float smf[];
    unsigned* q_s = (unsigned*)smf;        // [2][64][132]            = 16896 w
    unsigned* k_s = q_s + 16896;           // 2 bufs x [2][32][132]   = 16896 w
    unsigned* v_s = k_s + 16896;           // 2 bufs x [32][264]      = 16896 w

    const int tid   = threadIdx.x;
    const int lane  = tid & 31;
    const int w     = tid >> 5;
    const int g     = lane >> 2;
    const int t     = lane & 3;
    const int br    = w & 1;
    const int strip = w >> 1;
    const int mrow  = strip * 16;
    const int bh    = blockIdx.x;
    const int qt    = (int)gridDim.y - 1 - (int)blockIdx.y;  // big tiles first
    const int q0    = qt * 64;
    const int ntiles = 2 * qt + 2;

    const unsigned qsb = smem_u32(smf);
    const unsigned ksb = qsb + 16896u * 4;
    const unsigned vsb = ksb + 16896u * 4;

    const int b_ = bh >> 3, h_ = bh & 7;
    const float* q1b = g_q1 + (size_t)bh * Tt * HH;
    const float* q2b = g_q2 + (size_t)bh * Tt * HH;
    const float* k1b = g_k1 + (size_t)bh * Tt * HH;
    const float* k2b = g_k2 + (size_t)bh * Tt * HH;
    const float* vsrc = g_V + (size_t)(b_ * Tt) * Cc + h_ * HD;

    // Q tile: pure async copy (pre-scaled + pre-rounded)
    for (int i = tid; i < 4096; i += 256) {
        int bq = i >> 11;
        int r  = (i >> 5) & 63;
        int c4 = (i & 31) << 2;
        const float* src = (bq ? q2b : q1b) + (size_t)(q0 + r) * HH + c4;
        cp_async16(qsb + (unsigned)(bq * 8448 + r * 132 + c4) * 4, src);
    }
    // K/V tile 0 into buffer 0 (same group as Q)
    {
        for (int i = tid; i < 2048; i += 256) {
            int bq = i >> 10;
            int r  = (i >> 5) & 31;
            int c4 = (i & 31) << 2;
            const float* src = (bq ? k2b : k1b) + (size_t)r * HH + c4;
            cp_async16(ksb + (unsigned)(bq * 4224 + r * 132 + c4) * 4, src);
        }
        for (int i = tid; i < 2048; i += 256) {
            int r  = i >> 6;
            int c4 = (i & 63) << 2;
            cp_async16(vsb + (unsigned)(r * 264 + c4) * 4, vsrc + (size_t)r * Cc + c4);
        }
    }
    cp_commit();

    float oa[32][4];
#pragma unroll
    for (int i = 0; i < 32; i++) { oa[i][0]=0.f; oa[i][1]=0.f; oa[i][2]=0.f; oa[i][3]=0.f; }
    float m0 = -1e30f, m1 = -1e30f, l0 = 0.f, l1 = 0.f;

    for (int kb = 0; kb < ntiles; kb++) {
        const int buf = kb & 1;
        if (kb + 1 < ntiles) {
            const unsigned koff = (unsigned)((buf ^ 1) * 8448) * 4;
            const int kr = (kb + 1) * 32;
            for (int i = tid; i < 2048; i += 256) {
                int bq = i >> 10;
                int r  = (i >> 5) & 31;
                int c4 = (i & 31) << 2;
                const float* src = (bq ? k2b : k1b) + (size_t)(kr + r) * HH + c4;
                cp_async16(ksb + koff + (unsigned)(bq * 4224 + r * 132 + c4) * 4, src);
            }
            for (int i = tid; i < 2048; i += 256) {
                int r  = i >> 6;
                int c4 = (i & 63) << 2;
                cp_async16(vsb + koff + (unsigned)(r * 264 + c4) * 4,
                           vsrc + (size_t)(kr + r) * Cc + c4);
            }
        }
        cp_commit();
        asm volatile("cp.async.wait_group 1;");
        __syncthreads();

        // ---- S = Q K^T (16 rows x 32 keys, own branch) ----
        float sc[4][4];
#pragma unroll
        for (int nt = 0; nt < 4; nt++) { sc[nt][0]=0.f; sc[nt][1]=0.f; sc[nt][2]=0.f; sc[nt][3]=0.f; }
        {
            const unsigned* qb = q_s + br * 8448 + mrow * 132;
            const unsigned* kk = k_s + buf * 8448 + br * 4224;
#pragma unroll
            for (int ks = 0; ks < 16; ks++) {
                int col = 8 * ks + t;
                unsigned a[4];
                a[0] = qb[g * 132 + col];
                a[1] = qb[(g + 8) * 132 + col];
                a[2] = qb[g * 132 + col + 4];
                a[3] = qb[(g + 8) * 132 + col + 4];
#pragma unroll
                for (int nt = 0; nt < 4; nt++) {
                    unsigned bb[2];
                    bb[0] = kk[(8 * nt + g) * 132 + col];
                    bb[1] = kk[(8 * nt + g) * 132 + col + 4];
                    mma_tf32(sc[nt], a, bb);
                }
            }
        }

        // ---- causal mask (only tiles overlapping the diagonal block) ----
        if (kb >= 2 * qt) {
            int row0 = q0 + mrow + g;
            int row1 = row0 + 8;
#pragma unroll
            for (int nt = 0; nt < 4; nt++) {
                int kc = kb * 32 + 8 * nt + 2 * t;
                if (kc     > row0) sc[nt][0] = -1e30f;
                if (kc + 1 > row0) sc[nt][1] = -1e30f;
                if (kc     > row1) sc[nt][2] = -1e30f;
                if (kc + 1 > row1) sc[nt][3] = -1e30f;
            }
        }

        // ---- online softmax (base-2 domain), warp-local ----
        float mx0 = -1e30f, mx1 = -1e30f;
#pragma unroll
        for (int nt = 0; nt < 4; nt++) {
            mx0 = fmaxf(mx0, fmaxf(sc[nt][0], sc[nt][1]));
            mx1 = fmaxf(mx1, fmaxf(sc[nt][2], sc[nt][3]));
        }
        mx0 = fmaxf(mx0, __shfl_xor_sync(0xffffffffu, mx0, 1));
        mx0 = fmaxf(mx0, __shfl_xor_sync(0xffffffffu, mx0, 2));
        mx1 = fmaxf(mx1, __shfl_xor_sync(0xffffffffu, mx1, 1));
        mx1 = fmaxf(mx1, __shfl_xor_sync(0xffffffffu, mx1, 2));
        float nm0 = fmaxf(m0, mx0), nm1 = fmaxf(m1, mx1);
        float c0 = exp2f(m0 - nm0), c1 = exp2f(m1 - nm1);
        m0 = nm0; m1 = nm1;
        float s0 = 0.f, s1 = 0.f;
#pragma unroll
        for (int nt = 0; nt < 4; nt++) {
            sc[nt][0] = exp2f(sc[nt][0] - m0);
            sc[nt][1] = exp2f(sc[nt][1] - m0);
            sc[nt][2] = exp2f(sc[nt][2] - m1);
            sc[nt][3] = exp2f(sc[nt][3] - m1);
            s0 += sc[nt][0] + sc[nt][1];
            s1 += sc[nt][2] + sc[nt][3];
        }
        s0 += __shfl_xor_sync(0xffffffffu, s0, 1);
        s0 += __shfl_xor_sync(0xffffffffu, s0, 2);
        s1 += __shfl_xor_sync(0xffffffffu, s1, 1);
        s1 += __shfl_xor_sync(0xffffffffu, s1, 2);
        l0 = l0 * c0 + s0;
        l1 = l1 * c1 + s1;
        if (c0 != 1.f || c1 != 1.f) {
#pragma unroll
            for (int nt = 0; nt < 32; nt++) {
                oa[nt][0] *= c0; oa[nt][1] *= c0;
                oa[nt][2] *= c1; oa[nt][3] *= c1;
            }
        }

        // ---- P -> tf32 (rna, unbiased) ----
#pragma unroll
        for (int nt = 0; nt < 4; nt++) {
            sc[nt][0] = __uint_as_float(f2tf32(sc[nt][0]));
            sc[nt][1] = __uint_as_float(f2tf32(sc[nt][1]));
            sc[nt][2] = __uint_as_float(f2tf32(sc[nt][2]));
            sc[nt][3] = __uint_as_float(f2tf32(sc[nt][3]));
        }

        // ---- O += P V : C-frag -> A-frag via intra-group shfl ----
        const int srcA = (lane & ~3) | (t >> 1);
        const int srcB = (lane & ~3) | (((t >> 1) + 2) & 3);
        const unsigned* vv = v_s + buf * 8448;
#pragma unroll
        for (int kp = 0; kp < 4; kp++) {
            float x0  = __shfl_sync(0xffffffffu, sc[kp][0], srcA);
            float x1  = __shfl_sync(0xffffffffu, sc[kp][1], srcA);
            float y0  = __shfl_sync(0xffffffffu, sc[kp][2], srcA);
            float y1  = __shfl_sync(0xffffffffu, sc[kp][3], srcA);
            float x0b = __shfl_sync(0xffffffffu, sc[kp][0], srcB);
            float x1b = __shfl_sync(0xffffffffu, sc[kp][1], srcB);
            float y0b = __shfl_sync(0xffffffffu, sc[kp][2], srcB);
            float y1b = __shfl_sync(0xffffffffu, sc[kp][3], srcB);
            unsigned pa[4];
            pa[0] = __float_as_uint((t & 1) ? x1  : x0);
            pa[1] = __float_as_uint((t & 1) ? y1  : y0);
            pa[2] = __float_as_uint((t & 1) ? x1b : x0b);
            pa[3] = __float_as_uint((t & 1) ? y1b : y0b);
            const unsigned* v0r = vv + (8 * kp + t) * 264;
            const unsigned* v1r = vv + (8 * kp + t + 4) * 264;
#pragma unroll
            for (int nt = 0; nt < 32; nt++) {
                unsigned vb[2];
                vb[0] = v0r[8 * nt + g];
                vb[1] = v1r[8 * nt + g];
                mma_tf32(oa[nt], pa, vb);
            }
        }
        __syncthreads();
    }

    // ---- combine branches: y = O1/l1 - lam * O2/l2 (stored tf32-rounded) ----
    float* ex = smf;                       // reuse Q region
    float lam = g_lam;
    if (br == 0) {
        float r0 = 1.f / l0, r1 = 1.f / l1;
        float* eb = ex + strip * 4096;
#pragma unroll
        for (int nt = 0; nt < 32; nt++) {
            eb[(nt * 4 + 0) * 32 + lane] = oa[nt][0] * r0;
            eb[(nt * 4 + 1) * 32 + lane] = oa[nt][1] * r0;
            eb[(nt * 4 + 2) * 32 + lane] = oa[nt][2] * r1;
            eb[(nt * 4 + 3) * 32 + lane] = oa[nt][3] * r1;
        }
    }
    __syncthreads();
    if (br == 1) {
        float r0 = lam / l0, r1 = lam / l1;
        const float* eb = ex + strip * 4096;
        int row0 = q0 + mrow + g;
        float* y0p = g_y + ((size_t)(b_ * Tt) + row0) * Cc + h_ * HD;
        float* y1p = y0p + (size_t)8 * Cc;
#pragma unroll
        for (int nt = 0; nt < 32; nt++) {
            int col = 8 * nt + 2 * t;
            float2 o0, o1;
            o0.x = __uint_as_float(f2tf32(eb[(nt * 4 + 0) * 32 + lane] - oa[nt][0] * r0));
            o0.y = __uint_as_float(f2tf32(eb[(nt * 4 + 1) * 32 + lane] - oa[nt][1] * r0));
            o1.x = __uint_as_float(f2tf32(eb[(nt * 4 + 2) * 32 + lane] - oa[nt][2] * r1));
            o1.y = __uint_as_float(f2tf32(eb[(nt * 4 + 3) * 32 + lane] - oa[nt][3] * r1));
            *(float2*)(y0p + col) = o0;
            *(float2*)(y1p + col) = o1;
        }
    }
}

// ---------------- launcher ----------------
extern "C" void kernel_launch(void* const* d_in, const int* in_sizes, int n_in,
                              void* d_out, int out_size)
{
    const float* x   = (const float*)d_in[0];
    const float* wq  = (const float*)d_in[1];
    const float* wk  = (const float*)d_in[2];
    const float* wv  = (const float*)d_in[3];
    const float* wo  = (const float*)d_in[4];
    const float* lq1 = (const float*)d_in[5];
    const float* lk1 = (const float*)d_in[6];
    const float* lq2 = (const float*)d_in[7];
    const float* lk2 = (const float*)d_in[8];
    float* out = (float*)d_out;

    const int gsm = STG_W * 3 * 4;   // 110592 B
    cudaFuncSetAttribute(tgemm_qkv, cudaFuncAttributeMaxDynamicSharedMemorySize, gsm);
    cudaFuncSetAttribute(tgemm_wo,  cudaFuncAttributeMaxDynamicSharedMemorySize, gsm);

    cvt_kernel<<<dim3(4096, 1, 6), 256>>>(x, wq, wk, wv, wo);
    tgemm_qkv<<<dim3(Cc / 128, (Bsz * Tt) / 128, 3), 256, gsm>>>();
    lam_kernel<<<1, 256>>>(lq1, lk1, lq2, lk2);
    prep_kernel<<<Bsz * Tt * NH, 128>>>();

    int smem = 3 * 16896 * 4;   // 202752 B
    cudaFuncSetAttribute(attn_tc, cudaFuncAttributeMaxDynamicSharedMemorySize, smem);
    attn_tc<<<dim3(Bsz * NH, Tt / 64), 256, smem>>>();

    tgemm_wo<<<dim3(Cc / 128, (Bsz * Tt) / 128), 256, gsm>>>(out);
}